// round 13
// baseline (speedup 1.0000x reference)
#include <cuda_runtime.h>
#include <cstdint>

#define DIM   192
#define TDIM  576
#define WSZ   8
#define PIX   64
#define IMG   256
#define SHIFTV 4
#define NTHR  512

#define STRC  68
#define STRK  196
#define STRA  33

#define A_OFF  0      // qkv stage buf0 (10240) -> Vt[64][196] tf32 -> proj stage bufs
#define B_OFF  12544  // X tf32 [192][68] -> Q tf32 [192][68] -> attn-out tf32 [192][68]
#define C_OFF  25600  // qkv stage buf1 (10240) -> K tf32 [192][68]
#define D_OFF  38656  // rawV [192][68] -> As [192][33]
#define NS_OFF 51712  // Ns[0..191] q-norms, [192..383] k-norms
#define SMEM_FLOATS 52160

// swizzled chunk sizes (words)
#define QKV_CHUNK 10240   // 16k x 640o
#define PRJ_CHUNK 3072    // 16k x 192o

typedef unsigned long long ull;

__device__ uint32_t g_qkvK[12 * QKV_CHUNK];   // swizzled tf32
__device__ uint32_t g_projK[12 * PRJ_CHUNK];  // swizzled tf32

__device__ __forceinline__ uint32_t f2tf32(float f) {
    uint32_t u; asm("cvt.rna.tf32.f32 %0, %1;" : "=r"(u) : "f"(f)); return u;
}

// staged index for element (k-within-chunk kk16 in [0,16), o):
// ks=kk16>>3, tig=kk16&3, kh=(kk16>>2)&1 ; obase=o>>4, gid=o&7, o8=(o>>3)&1
__device__ __forceinline__ int swz_idx(int kk16, int o, int ks_stride) {
    int ks = kk16 >> 3, tig = kk16 & 3, kh = (kk16 >> 2) & 1;
    int obase = o >> 4, gid = o & 7, o8 = (o >> 3) & 1;
    return ks * ks_stride + obase * 128 + tig * 32 + gid * 4 + kh * 2 + o8;
}

__global__ void wtrans_kernel(const float* __restrict__ qkv_w,
                              const float* __restrict__ proj_w) {
    int i = blockIdx.x * 256 + threadIdx.x;
    if (i < 640 * DIM) {           // (o, c) over padded qkv
        int o = i / DIM, c = i % DIM;
        int chunk = c >> 4, kk16 = c & 15;
        int idx = chunk * QKV_CHUNK + swz_idx(kk16, o, 5120);
        g_qkvK[idx] = (o < TDIM) ? f2tf32(qkv_w[o * DIM + c]) : 0u;
    }
    if (i < DIM * DIM) {           // (o, c) over proj
        int o = i / DIM, c = i % DIM;
        int chunk = c >> 4, kk16 = c & 15;
        int idx = chunk * PRJ_CHUNK + swz_idx(kk16, o, 1536);
        g_projK[idx] = f2tf32(proj_w[o * DIM + c]);
    }
}

__device__ __forceinline__ void mma16n8k8(float* d, const uint32_t* a, const uint32_t* b) {
    asm volatile(
        "mma.sync.aligned.m16n8k8.row.col.f32.tf32.tf32.f32 "
        "{%0,%1,%2,%3}, {%4,%5,%6,%7}, {%8,%9}, {%0,%1,%2,%3};"
        : "+f"(d[0]), "+f"(d[1]), "+f"(d[2]), "+f"(d[3])
        : "r"(a[0]), "r"(a[1]), "r"(a[2]), "r"(a[3]), "r"(b[0]), "r"(b[1]));
}
__device__ __forceinline__ uint32_t smem_u32(const void* p) {
    uint32_t a;
    asm("{ .reg .u64 t; cvta.to.shared.u64 t, %1; cvt.u32.u64 %0, t; }" : "=r"(a) : "l"(p));
    return a;
}
__device__ __forceinline__ void cp16(uint32_t saddr, const void* g) {
    asm volatile("cp.async.cg.shared.global [%0], [%1], 16;" :: "r"(saddr), "l"(g));
}
__device__ __forceinline__ void cp_commit() {
    asm volatile("cp.async.commit_group;" ::: "memory");
}
template <int N>
__device__ __forceinline__ void cp_wait() {
    asm volatile("cp.async.wait_group %0;" :: "n"(N) : "memory");
}
__device__ __forceinline__ void lds128(uint32_t* r, uint32_t saddr) {
    asm volatile("ld.shared.v4.b32 {%0,%1,%2,%3}, [%4];"
                 : "=r"(r[0]), "=r"(r[1]), "=r"(r[2]), "=r"(r[3]) : "r"(saddr));
}

__global__ void __launch_bounds__(NTHR, 1)
attn_kernel(const float* __restrict__ x, const float* __restrict__ dw_w,
            const float* __restrict__ temperature, float* __restrict__ out) {
    extern __shared__ float sm[];
    float* Ra = sm + A_OFF;
    float* Rb = sm + B_OFF;
    float* Rc = sm + C_OFF;
    float* Rd = sm + D_OFF;
    float* Ns = sm + NS_OFF;

    const int tid = threadIdx.x;
    const int win = blockIdx.x;
    const int bi = win >> 10;
    const int wh = (win >> 5) & 31;
    const int ww = win & 31;
    const int lane = tid & 31;
    const int wid = tid >> 5;
    const uint32_t sbase = smem_u32(sm);
    const uint32_t sRa = sbase + A_OFF * 4;
    const uint32_t sRc = sbase + C_OFF * 4;

    // ---- load window with roll(-4,-4) into Rb as tf32 bits [192][68] ----
    {
        const float* xb = x + (size_t)bi * DIM * IMG * IMG;
        uint32_t* Xu = (uint32_t*)Rb;
        for (int e = tid; e < DIM * PIX; e += NTHR) {
            int c = e >> 6, p = e & 63;
            int i = p >> 3, j = p & 7;
            int gh = (wh * WSZ + i + SHIFTV) & 255;
            int gw = (ww * WSZ + j + SHIFTV) & 255;
            Xu[c * STRC + p] = f2tf32(xb[(c * IMG + gh) * IMG + gw]);
        }
    }

    // ---- qkv GEMM via mma.sync tf32, swizzled A chunks staged by cp.async ----
    {
        const uint32_t* Xu = (const uint32_t*)Rb;
        const int gid = lane >> 2, tig = lane & 3;
        const int mg = wid >> 1, ng = wid & 1;
        float dacc[5][4][4];
#pragma unroll
        for (int mt = 0; mt < 5; mt++)
#pragma unroll
            for (int nt = 0; nt < 4; nt++)
#pragma unroll
                for (int q = 0; q < 4; q++) dacc[mt][nt][q] = 0.f;

        // prologue: stage chunk 0 into buf0 (Ra)
        for (int e = tid; e < QKV_CHUNK / 4; e += NTHR)
            cp16(sRa + e * 16, g_qkvK + e * 4);
        cp_commit();
        cp_wait<0>();
        __syncthreads();

        for (int kc = 0; kc < 12; kc++) {
            const uint32_t sW = (kc & 1) ? sRc : sRa;
            if (kc < 11) {
                uint32_t sN = (kc & 1) ? sRa : sRc;
                const uint32_t* src = g_qkvK + (kc + 1) * QKV_CHUNK;
                for (int e = tid; e < QKV_CHUNK / 4; e += NTHR)
                    cp16(sN + e * 16, src + e * 4);
                cp_commit();
            }
#pragma unroll
            for (int ks = 0; ks < 2; ks++) {
                const int kk = ks * 8;
                uint32_t breg[4][2];
#pragma unroll
                for (int nt = 0; nt < 4; nt++) {
                    int col = ng * 32 + nt * 8 + gid;
                    breg[nt][0] = Xu[(kc * 16 + kk + tig) * STRC + col];
                    breg[nt][1] = Xu[(kc * 16 + kk + tig + 4) * STRC + col];
                }
#pragma unroll
                for (int mt = 0; mt < 5; mt++) {
                    uint32_t areg[4];
                    lds128(areg, sW + (ks * 5120 + (mg * 5 + mt) * 128 + tig * 32 + gid * 4) * 4);
#pragma unroll
                    for (int nt = 0; nt < 4; nt++)
                        mma16n8k8(dacc[mt][nt], areg, breg[nt]);
                }
            }
            if (kc < 11) cp_wait<0>();
            __syncthreads();
        }

#pragma unroll
        for (int mt = 0; mt < 5; mt++) {
#pragma unroll
            for (int half = 0; half < 2; half++) {
                int o = mg * 80 + mt * 16 + gid + half * 8;
                if (o < TDIM) {
                    int s = o / DIM, ch = o - s * DIM;
                    float* dst = (s == 0 ? Rb : s == 1 ? Rc : Rd) + ch * STRC + ng * 32 + 2 * tig;
#pragma unroll
                    for (int nt = 0; nt < 4; nt++)
                        *(float2*)(dst + nt * 8) =
                            make_float2(dacc[mt][nt][half * 2], dacc[mt][nt][half * 2 + 1]);
                }
            }
        }
    }
    __syncthreads();

    // ---- dwconv: Q (Rb) and K (Rc) in place with norms; V (Rd) -> Vt (Ra) ----
    {
#pragma unroll
        for (int it = 0; it < 6; it++) {
            int t = it * NTHR + tid;
            int ch_ = t >> 3, row = t & 7;
            int isQ = ch_ < DIM;
            float* rr = (isQ ? Rb : Rc) + (isQ ? ch_ : ch_ - DIM) * STRC;
            const float* wd = dw_w + (size_t)ch_ * 9;
            float w0 = __ldg(wd+0), w1 = __ldg(wd+1), w2 = __ldg(wd+2);
            float w3 = __ldg(wd+3), w4 = __ldg(wd+4), w5 = __ldg(wd+5);
            float w6 = __ldg(wd+6), w7 = __ldg(wd+7), w8 = __ldg(wd+8);
            float A[8], B[8], C[8];
            {
                const float4* r4 = (const float4*)(rr + row * 8);
                float4 b0 = r4[0], b1 = r4[1];
                B[0]=b0.x; B[1]=b0.y; B[2]=b0.z; B[3]=b0.w;
                B[4]=b1.x; B[5]=b1.y; B[6]=b1.z; B[7]=b1.w;
            }
            if (row > 0) {
                const float4* r4 = (const float4*)(rr + (row - 1) * 8);
                float4 a0 = r4[0], a1 = r4[1];
                A[0]=a0.x; A[1]=a0.y; A[2]=a0.z; A[3]=a0.w;
                A[4]=a1.x; A[5]=a1.y; A[6]=a1.z; A[7]=a1.w;
            } else {
#pragma unroll
                for (int j = 0; j < 8; j++) A[j] = 0.f;
            }
            if (row < 7) {
                const float4* r4 = (const float4*)(rr + (row + 1) * 8);
                float4 c0 = r4[0], c1 = r4[1];
                C[0]=c0.x; C[1]=c0.y; C[2]=c0.z; C[3]=c0.w;
                C[4]=c1.x; C[5]=c1.y; C[6]=c1.z; C[7]=c1.w;
            } else {
#pragma unroll
                for (int j = 0; j < 8; j++) C[j] = 0.f;
            }
            float o[8];
            float ss = 0.f;
#pragma unroll
            for (int j = 0; j < 8; j++) {
                float s = w1 * A[j] + w4 * B[j] + w7 * C[j];
                if (j > 0) s += w0 * A[j-1] + w3 * B[j-1] + w6 * C[j-1];
                if (j < 7) s += w2 * A[j+1] + w5 * B[j+1] + w8 * C[j+1];
                o[j] = s;
                ss += s * s;
            }
            ss += __shfl_xor_sync(0xffffffffu, ss, 4);
            ss += __shfl_xor_sync(0xffffffffu, ss, 2);
            ss += __shfl_xor_sync(0xffffffffu, ss, 1);
            __syncwarp();
            float4* w4p = (float4*)(rr + row * 8);
            w4p[0] = make_float4(__uint_as_float(f2tf32(o[0])), __uint_as_float(f2tf32(o[1])),
                                 __uint_as_float(f2tf32(o[2])), __uint_as_float(f2tf32(o[3])));
            w4p[1] = make_float4(__uint_as_float(f2tf32(o[4])), __uint_as_float(f2tf32(o[5])),
                                 __uint_as_float(f2tf32(o[6])), __uint_as_float(f2tf32(o[7])));
            if ((lane & 7) == 0)
                Ns[ch_] = 1.f / fmaxf(sqrtf(ss), 1e-12f);
            __syncwarp();
        }
        // V -> transposed Vt in Ra (tf32)
#pragma unroll
        for (int it = 0; it < 3; it++) {
            int task = it * NTHR + tid;
            int ch = task % DIM;
            int row = task / DIM;
            const float* rr = Rd + ch * STRC;
            const float* wd = dw_w + (size_t)(2 * DIM + ch) * 9;
            float w0 = __ldg(wd+0), w1 = __ldg(wd+1), w2 = __ldg(wd+2);
            float w3 = __ldg(wd+3), w4 = __ldg(wd+4), w5 = __ldg(wd+5);
            float w6 = __ldg(wd+6), w7 = __ldg(wd+7), w8 = __ldg(wd+8);
            float A[8], B[8], C[8];
            {
                const float4* r4 = (const float4*)(rr + row * 8);
                float4 b0 = r4[0], b1 = r4[1];
                B[0]=b0.x; B[1]=b0.y; B[2]=b0.z; B[3]=b0.w;
                B[4]=b1.x; B[5]=b1.y; B[6]=b1.z; B[7]=b1.w;
            }
            if (row > 0) {
                const float4* r4 = (const float4*)(rr + (row - 1) * 8);
                float4 a0 = r4[0], a1 = r4[1];
                A[0]=a0.x; A[1]=a0.y; A[2]=a0.z; A[3]=a0.w;
                A[4]=a1.x; A[5]=a1.y; A[6]=a1.z; A[7]=a1.w;
            } else {
#pragma unroll
                for (int j = 0; j < 8; j++) A[j] = 0.f;
            }
            if (row < 7) {
                const float4* r4 = (const float4*)(rr + (row + 1) * 8);
                float4 c0 = r4[0], c1 = r4[1];
                C[0]=c0.x; C[1]=c0.y; C[2]=c0.z; C[3]=c0.w;
                C[4]=c1.x; C[5]=c1.y; C[6]=c1.z; C[7]=c1.w;
            } else {
#pragma unroll
                for (int j = 0; j < 8; j++) C[j] = 0.f;
            }
#pragma unroll
            for (int j = 0; j < 8; j++) {
                float s = w1 * A[j] + w4 * B[j] + w7 * C[j];
                if (j > 0) s += w0 * A[j-1] + w3 * B[j-1] + w6 * C[j-1];
                if (j < 7) s += w2 * A[j+1] + w5 * B[j+1] + w8 * C[j+1];
                Ra[(row * 8 + j) * STRK + ch] = __uint_as_float(f2tf32(s));
            }
        }
    }
    __syncthreads();

    // ---- scores via mma.sync: S = q @ k^T per head -> As (Rd) ----
    {
        const uint32_t* Qu = (const uint32_t*)Rb;
        const uint32_t* Ku = (const uint32_t*)Rc;
        float* As = Rd;
        const int gid = lane >> 2, tig = lane & 3;
#pragma unroll
        for (int i = 0; i < 3; i++) {
            int t = wid + 16 * i;
            int head = t >> 3, mt = (t >> 2) & 1, nt = t & 3;
            int bm = head * 32 + mt * 16, bn = head * 32 + nt * 8;
            float dacc[4] = {0.f, 0.f, 0.f, 0.f};
#pragma unroll
            for (int kc = 0; kc < 8; kc++) {
                int kk = kc * 8;
                uint32_t areg[4], breg[2];
                areg[0] = Qu[(bm + gid) * STRC + kk + tig];
                areg[1] = Qu[(bm + gid + 8) * STRC + kk + tig];
                areg[2] = Qu[(bm + gid) * STRC + kk + tig + 4];
                areg[3] = Qu[(bm + gid + 8) * STRC + kk + tig + 4];
                breg[0] = Ku[(bn + gid) * STRC + kk + tig];
                breg[1] = Ku[(bn + gid) * STRC + kk + tig + 4];
                mma16n8k8(dacc, areg, breg);
            }
            float tmp = __ldg(temperature + head);
            float iq0 = Ns[bm + gid] * tmp, iq8 = Ns[bm + gid + 8] * tmp;
            float ik0 = Ns[DIM + bn + 2 * tig], ik1 = Ns[DIM + bn + 2 * tig + 1];
            int dn = nt * 8 + 2 * tig;
            As[(bm + gid) * STRA + dn]         = dacc[0] * iq0 * ik0;
            As[(bm + gid) * STRA + dn + 1]     = dacc[1] * iq0 * ik1;
            As[(bm + gid + 8) * STRA + dn]     = dacc[2] * iq8 * ik0;
            As[(bm + gid + 8) * STRA + dn + 1] = dacc[3] * iq8 * ik1;
        }
    }
    __syncthreads();

    // ---- softmax over d; store tf32-rounded ----
    if (tid < DIM) {
        float* arow = Rd + tid * STRA;
        float m = arow[0];
#pragma unroll
        for (int d = 1; d < 32; d++) m = fmaxf(m, arow[d]);
        float s = 0.f;
        float ev[32];
#pragma unroll
        for (int d = 0; d < 32; d++) { ev[d] = expf(arow[d] - m); s += ev[d]; }
        float inv = 1.f / s;
#pragma unroll
        for (int d = 0; d < 32; d++) arow[d] = __uint_as_float(f2tf32(ev[d] * inv));
    }
    __syncthreads();

    // ---- attn@v via mma.sync: O = A @ V -> Rb tf32 [192][68] ----
    {
        const uint32_t* Au = (const uint32_t*)Rd;
        const uint32_t* Vu = (const uint32_t*)Ra;
        uint32_t* Ou = (uint32_t*)Rb;
        const int gid = lane >> 2, tig = lane & 3;
#pragma unroll
        for (int i = 0; i < 6; i++) {
            int t = wid + 16 * i;
            int head = t >> 4, mt = (t >> 3) & 1, nt = t & 7;
            int bm = head * 32 + mt * 16, bn = nt * 8;
            float dacc[4] = {0.f, 0.f, 0.f, 0.f};
#pragma unroll
            for (int kc = 0; kc < 4; kc++) {
                int kk = kc * 8;
                uint32_t areg[4], breg[2];
                areg[0] = Au[(bm + gid) * STRA + kk + tig];
                areg[1] = Au[(bm + gid + 8) * STRA + kk + tig];
                areg[2] = Au[(bm + gid) * STRA + kk + tig + 4];
                areg[3] = Au[(bm + gid + 8) * STRA + kk + tig + 4];
                breg[0] = Vu[(bn + gid) * STRK + head * 32 + kk + tig];
                breg[1] = Vu[(bn + gid) * STRK + head * 32 + kk + tig + 4];
                mma16n8k8(dacc, areg, breg);
            }
            Ou[(bm + gid) * STRC + bn + 2 * tig]         = f2tf32(dacc[0]);
            Ou[(bm + gid) * STRC + bn + 2 * tig + 1]     = f2tf32(dacc[1]);
            Ou[(bm + gid + 8) * STRC + bn + 2 * tig]     = f2tf32(dacc[2]);
            Ou[(bm + gid + 8) * STRC + bn + 2 * tig + 1] = f2tf32(dacc[3]);
        }
    }
    __syncthreads();

    // ---- proj GEMM via mma.sync tf32, swizzled A staged by cp.async in Ra ----
    {
        const uint32_t* Xu = (const uint32_t*)Rb;
        const int gid = lane >> 2, tig = lane & 3;
        const int mgr = wid >> 2, ngr = wid & 3;
        float dacc[3][2][4];
#pragma unroll
        for (int mt = 0; mt < 3; mt++)
#pragma unroll
            for (int nt = 0; nt < 2; nt++)
#pragma unroll
                for (int q = 0; q < 4; q++) dacc[mt][nt][q] = 0.f;

        for (int e = tid; e < PRJ_CHUNK / 4; e += NTHR)
            cp16(sRa + e * 16, g_projK + e * 4);
        cp_commit();
        cp_wait<0>();
        __syncthreads();

        for (int kc = 0; kc < 12; kc++) {
            const uint32_t sW = sRa + (kc & 1) * PRJ_CHUNK * 4;
            if (kc < 11) {
                uint32_t sN = sRa + ((kc + 1) & 1) * PRJ_CHUNK * 4;
                const uint32_t* src = g_projK + (kc + 1) * PRJ_CHUNK;
                for (int e = tid; e < PRJ_CHUNK / 4; e += NTHR)
                    cp16(sN + e * 16, src + e * 4);
                cp_commit();
            }
#pragma unroll
            for (int ks = 0; ks < 2; ks++) {
                const int kk = ks * 8;
                uint32_t breg[2][2];
#pragma unroll
                for (int nt = 0; nt < 2; nt++) {
                    int col = ngr * 16 + nt * 8 + gid;
                    breg[nt][0] = Xu[(kc * 16 + kk + tig) * STRC + col];
                    breg[nt][1] = Xu[(kc * 16 + kk + tig + 4) * STRC + col];
                }
#pragma unroll
                for (int mt = 0; mt < 3; mt++) {
                    uint32_t areg[4];
                    lds128(areg, sW + (ks * 1536 + (mgr * 3 + mt) * 128 + tig * 32 + gid * 4) * 4);
#pragma unroll
                    for (int nt = 0; nt < 2; nt++)
                        mma16n8k8(dacc[mt][nt], areg, breg[nt]);
                }
            }
            if (kc < 11) cp_wait<0>();
            __syncthreads();
        }

        // epilogue: fragments -> gmem with roll(+4,+4)
#pragma unroll
        for (int mt = 0; mt < 3; mt++) {
#pragma unroll
            for (int half = 0; half < 2; half++) {
                int o = mgr * 48 + mt * 16 + gid + half * 8;
                float* obase = out + ((size_t)(bi * DIM + o) * IMG) * IMG;
#pragma unroll
                for (int nt = 0; nt < 2; nt++) {
                    int p = ngr * 16 + nt * 8 + 2 * tig;
                    int i = p >> 3, j = p & 7;
                    int gh = (wh * WSZ + i + SHIFTV) & 255;
                    int gw0 = (ww * WSZ + j + SHIFTV) & 255;
                    int gw1 = (ww * WSZ + j + 1 + SHIFTV) & 255;
                    obase[gh * IMG + gw0] = dacc[mt][nt][half * 2];
                    obase[gh * IMG + gw1] = dacc[mt][nt][half * 2 + 1];
                }
            }
        }
    }
}

extern "C" void kernel_launch(void* const* d_in, const int* in_sizes, int n_in,
                              void* d_out, int out_size) {
    const float* x           = (const float*)d_in[0];
    const float* qkv_w       = (const float*)d_in[1];
    const float* dw_w        = (const float*)d_in[2];
    const float* proj_w      = (const float*)d_in[3];
    const float* temperature = (const float*)d_in[4];
    float* out = (float*)d_out;

    cudaFuncSetAttribute(attn_kernel, cudaFuncAttributeMaxDynamicSharedMemorySize,
                         SMEM_FLOATS * 4);
    wtrans_kernel<<<(640 * DIM + 255) / 256, 256>>>(qkv_w, proj_w);
    attn_kernel<<<4096, NTHR, SMEM_FLOATS * 4>>>(x, dw_w, temperature, out);
}

// round 14
// speedup vs baseline: 1.3586x; 1.3586x over previous
#include <cuda_runtime.h>
#include <cstdint>

#define DIM   192
#define TDIM  576
#define WSZ   8
#define PIX   64
#define IMG   256
#define SHIFTV 4
#define NTHR  512

#define STRC  68
#define STRK  196
#define STRA  33

#define A_OFF  0      // qkv stage buf0 (10240) -> Vt[64][196] tf32 -> proj stage bufs
#define B_OFF  12544  // X tf32 [192][68] -> Q tf32 [192][68] -> attn-out tf32 [192][68]
#define C_OFF  25600  // qkv stage buf1 (10240) -> K tf32 [192][68]
#define D_OFF  38656  // rawV [192][68] -> As [192][33]
#define NS_OFF 51712  // Ns[0..191] q-norms, [192..383] k-norms
#define SMEM_FLOATS 52160

#define QKV_CHUNK 10240   // 16k x 640o (words)
#define PRJ_CHUNK 3072    // 16k x 192o (words)

typedef unsigned long long ull;

__device__ uint32_t g_qkvK[12 * QKV_CHUNK];   // swizzled tf32
__device__ uint32_t g_projK[12 * PRJ_CHUNK];  // swizzled tf32

__device__ __forceinline__ uint32_t f2tf32(float f) {
    uint32_t u; asm("cvt.rna.tf32.f32 %0, %1;" : "=r"(u) : "f"(f)); return u;
}

// lane-ordered fragment layout: for (ks, 16-o tile), 128-word block is
// block[lane*4 + kh*2 + o8], lane = gid*4 + tig  -> quarter-warp reads 128B
// contiguous (conflict-free LDS.128), quad == exact m16n8k8 A fragment.
__device__ __forceinline__ int swz_idx(int kk16, int o, int ks_stride) {
    int ks = kk16 >> 3, tig = kk16 & 3, kh = (kk16 >> 2) & 1;
    int obase = o >> 4, gid = o & 7, o8 = (o >> 3) & 1;
    return ks * ks_stride + obase * 128 + (gid * 4 + tig) * 4 + kh * 2 + o8;
}

__global__ void wtrans_kernel(const float* __restrict__ qkv_w,
                              const float* __restrict__ proj_w) {
    int i = blockIdx.x * 256 + threadIdx.x;
    if (i < 640 * DIM) {
        int o = i / DIM, c = i % DIM;
        int chunk = c >> 4, kk16 = c & 15;
        int idx = chunk * QKV_CHUNK + swz_idx(kk16, o, 5120);
        g_qkvK[idx] = (o < TDIM) ? f2tf32(qkv_w[o * DIM + c]) : 0u;
    }
    if (i < DIM * DIM) {
        int o = i / DIM, c = i % DIM;
        int chunk = c >> 4, kk16 = c & 15;
        int idx = chunk * PRJ_CHUNK + swz_idx(kk16, o, 1536);
        g_projK[idx] = f2tf32(proj_w[o * DIM + c]);
    }
}

__device__ __forceinline__ void mma16n8k8(float* d, const uint32_t* a, const uint32_t* b) {
    asm volatile(
        "mma.sync.aligned.m16n8k8.row.col.f32.tf32.tf32.f32 "
        "{%0,%1,%2,%3}, {%4,%5,%6,%7}, {%8,%9}, {%0,%1,%2,%3};"
        : "+f"(d[0]), "+f"(d[1]), "+f"(d[2]), "+f"(d[3])
        : "r"(a[0]), "r"(a[1]), "r"(a[2]), "r"(a[3]), "r"(b[0]), "r"(b[1]));
}
__device__ __forceinline__ uint32_t smem_u32(const void* p) {
    uint32_t a;
    asm("{ .reg .u64 t; cvta.to.shared.u64 t, %1; cvt.u32.u64 %0, t; }" : "=r"(a) : "l"(p));
    return a;
}
__device__ __forceinline__ void cp16(uint32_t saddr, const void* g) {
    asm volatile("cp.async.cg.shared.global [%0], [%1], 16;" :: "r"(saddr), "l"(g));
}
__device__ __forceinline__ void cp_commit() {
    asm volatile("cp.async.commit_group;" ::: "memory");
}
template <int N>
__device__ __forceinline__ void cp_wait() {
    asm volatile("cp.async.wait_group %0;" :: "n"(N) : "memory");
}
__device__ __forceinline__ void lds128(uint32_t* r, uint32_t saddr) {
    asm volatile("ld.shared.v4.b32 {%0,%1,%2,%3}, [%4];"
                 : "=r"(r[0]), "=r"(r[1]), "=r"(r[2]), "=r"(r[3]) : "r"(saddr));
}

__global__ void __launch_bounds__(NTHR, 1)
attn_kernel(const float* __restrict__ x, const float* __restrict__ dw_w,
            const float* __restrict__ temperature, float* __restrict__ out) {
    extern __shared__ float sm[];
    float* Ra = sm + A_OFF;
    float* Rb = sm + B_OFF;
    float* Rc = sm + C_OFF;
    float* Rd = sm + D_OFF;
    float* Ns = sm + NS_OFF;

    const int tid = threadIdx.x;
    const int win = blockIdx.x;
    const int bi = win >> 10;
    const int wh = (win >> 5) & 31;
    const int ww = win & 31;
    const int lane = tid & 31;
    const int wid = tid >> 5;
    const uint32_t sbase = smem_u32(sm);
    const uint32_t sRa = sbase + A_OFF * 4;
    const uint32_t sRc = sbase + C_OFF * 4;

    // ---- load window with roll(-4,-4) into Rb as tf32 bits [192][68] ----
    {
        const float* xb = x + (size_t)bi * DIM * IMG * IMG;
        uint32_t* Xu = (uint32_t*)Rb;
        for (int e = tid; e < DIM * PIX; e += NTHR) {
            int c = e >> 6, p = e & 63;
            int i = p >> 3, j = p & 7;
            int gh = (wh * WSZ + i + SHIFTV) & 255;
            int gw = (ww * WSZ + j + SHIFTV) & 255;
            Xu[c * STRC + p] = f2tf32(xb[(c * IMG + gh) * IMG + gw]);
        }
    }

    // ---- qkv GEMM via mma.sync tf32, swizzled A chunks staged by cp.async ----
    {
        const uint32_t* Xu = (const uint32_t*)Rb;
        const int gid = lane >> 2, tig = lane & 3;
        const int mg = wid >> 1, ng = wid & 1;
        float dacc[5][4][4];
#pragma unroll
        for (int mt = 0; mt < 5; mt++)
#pragma unroll
            for (int nt = 0; nt < 4; nt++)
#pragma unroll
                for (int q = 0; q < 4; q++) dacc[mt][nt][q] = 0.f;

        for (int e = tid; e < QKV_CHUNK / 4; e += NTHR)
            cp16(sRa + e * 16, g_qkvK + e * 4);
        cp_commit();
        cp_wait<0>();
        __syncthreads();

        for (int kc = 0; kc < 12; kc++) {
            const uint32_t sW = (kc & 1) ? sRc : sRa;
            if (kc < 11) {
                uint32_t sN = (kc & 1) ? sRa : sRc;
                const uint32_t* src = g_qkvK + (kc + 1) * QKV_CHUNK;
                for (int e = tid; e < QKV_CHUNK / 4; e += NTHR)
                    cp16(sN + e * 16, src + e * 4);
                cp_commit();
            }
#pragma unroll
            for (int ks = 0; ks < 2; ks++) {
                const int kk = ks * 8;
                uint32_t breg[4][2];
#pragma unroll
                for (int nt = 0; nt < 4; nt++) {
                    int col = ng * 32 + nt * 8 + gid;
                    breg[nt][0] = Xu[(kc * 16 + kk + tig) * STRC + col];
                    breg[nt][1] = Xu[(kc * 16 + kk + tig + 4) * STRC + col];
                }
#pragma unroll
                for (int mt = 0; mt < 5; mt++) {
                    uint32_t areg[4];
                    lds128(areg, sW + (ks * 5120 + (mg * 5 + mt) * 128 + lane * 4) * 4);
#pragma unroll
                    for (int nt = 0; nt < 4; nt++)
                        mma16n8k8(dacc[mt][nt], areg, breg[nt]);
                }
            }
            if (kc < 11) cp_wait<0>();
            __syncthreads();
        }

#pragma unroll
        for (int mt = 0; mt < 5; mt++) {
#pragma unroll
            for (int half = 0; half < 2; half++) {
                int o = mg * 80 + mt * 16 + gid + half * 8;
                if (o < TDIM) {
                    int s = o / DIM, ch = o - s * DIM;
                    float* dst = (s == 0 ? Rb : s == 1 ? Rc : Rd) + ch * STRC + ng * 32 + 2 * tig;
#pragma unroll
                    for (int nt = 0; nt < 4; nt++)
                        *(float2*)(dst + nt * 8) =
                            make_float2(dacc[mt][nt][half * 2], dacc[mt][nt][half * 2 + 1]);
                }
            }
        }
    }
    __syncthreads();

    // ---- dwconv: Q (Rb) and K (Rc) in place with norms; V (Rd) -> Vt (Ra) ----
    {
#pragma unroll
        for (int it = 0; it < 6; it++) {
            int t = it * NTHR + tid;
            int ch_ = t >> 3, row = t & 7;
            int isQ = ch_ < DIM;
            float* rr = (isQ ? Rb : Rc) + (isQ ? ch_ : ch_ - DIM) * STRC;
            const float* wd = dw_w + (size_t)ch_ * 9;
            float w0 = __ldg(wd+0), w1 = __ldg(wd+1), w2 = __ldg(wd+2);
            float w3 = __ldg(wd+3), w4 = __ldg(wd+4), w5 = __ldg(wd+5);
            float w6 = __ldg(wd+6), w7 = __ldg(wd+7), w8 = __ldg(wd+8);
            float A[8], B[8], C[8];
            {
                const float4* r4 = (const float4*)(rr + row * 8);
                float4 b0 = r4[0], b1 = r4[1];
                B[0]=b0.x; B[1]=b0.y; B[2]=b0.z; B[3]=b0.w;
                B[4]=b1.x; B[5]=b1.y; B[6]=b1.z; B[7]=b1.w;
            }
            if (row > 0) {
                const float4* r4 = (const float4*)(rr + (row - 1) * 8);
                float4 a0 = r4[0], a1 = r4[1];
                A[0]=a0.x; A[1]=a0.y; A[2]=a0.z; A[3]=a0.w;
                A[4]=a1.x; A[5]=a1.y; A[6]=a1.z; A[7]=a1.w;
            } else {
#pragma unroll
                for (int j = 0; j < 8; j++) A[j] = 0.f;
            }
            if (row < 7) {
                const float4* r4 = (const float4*)(rr + (row + 1) * 8);
                float4 c0 = r4[0], c1 = r4[1];
                C[0]=c0.x; C[1]=c0.y; C[2]=c0.z; C[3]=c0.w;
                C[4]=c1.x; C[5]=c1.y; C[6]=c1.z; C[7]=c1.w;
            } else {
#pragma unroll
                for (int j = 0; j < 8; j++) C[j] = 0.f;
            }
            float o[8];
            float ss = 0.f;
#pragma unroll
            for (int j = 0; j < 8; j++) {
                float s = w1 * A[j] + w4 * B[j] + w7 * C[j];
                if (j > 0) s += w0 * A[j-1] + w3 * B[j-1] + w6 * C[j-1];
                if (j < 7) s += w2 * A[j+1] + w5 * B[j+1] + w8 * C[j+1];
                o[j] = s;
                ss += s * s;
            }
            ss += __shfl_xor_sync(0xffffffffu, ss, 4);
            ss += __shfl_xor_sync(0xffffffffu, ss, 2);
            ss += __shfl_xor_sync(0xffffffffu, ss, 1);
            __syncwarp();
            float4* w4p = (float4*)(rr + row * 8);
            w4p[0] = make_float4(__uint_as_float(f2tf32(o[0])), __uint_as_float(f2tf32(o[1])),
                                 __uint_as_float(f2tf32(o[2])), __uint_as_float(f2tf32(o[3])));
            w4p[1] = make_float4(__uint_as_float(f2tf32(o[4])), __uint_as_float(f2tf32(o[5])),
                                 __uint_as_float(f2tf32(o[6])), __uint_as_float(f2tf32(o[7])));
            if ((lane & 7) == 0)
                Ns[ch_] = 1.f / fmaxf(sqrtf(ss), 1e-12f);
            __syncwarp();
        }
        // V -> transposed Vt in Ra (tf32)
#pragma unroll
        for (int it = 0; it < 3; it++) {
            int task = it * NTHR + tid;
            int ch = task % DIM;
            int row = task / DIM;
            const float* rr = Rd + ch * STRC;
            const float* wd = dw_w + (size_t)(2 * DIM + ch) * 9;
            float w0 = __ldg(wd+0), w1 = __ldg(wd+1), w2 = __ldg(wd+2);
            float w3 = __ldg(wd+3), w4 = __ldg(wd+4), w5 = __ldg(wd+5);
            float w6 = __ldg(wd+6), w7 = __ldg(wd+7), w8 = __ldg(wd+8);
            float A[8], B[8], C[8];
            {
                const float4* r4 = (const float4*)(rr + row * 8);
                float4 b0 = r4[0], b1 = r4[1];
                B[0]=b0.x; B[1]=b0.y; B[2]=b0.z; B[3]=b0.w;
                B[4]=b1.x; B[5]=b1.y; B[6]=b1.z; B[7]=b1.w;
            }
            if (row > 0) {
                const float4* r4 = (const float4*)(rr + (row - 1) * 8);
                float4 a0 = r4[0], a1 = r4[1];
                A[0]=a0.x; A[1]=a0.y; A[2]=a0.z; A[3]=a0.w;
                A[4]=a1.x; A[5]=a1.y; A[6]=a1.z; A[7]=a1.w;
            } else {
#pragma unroll
                for (int j = 0; j < 8; j++) A[j] = 0.f;
            }
            if (row < 7) {
                const float4* r4 = (const float4*)(rr + (row + 1) * 8);
                float4 c0 = r4[0], c1 = r4[1];
                C[0]=c0.x; C[1]=c0.y; C[2]=c0.z; C[3]=c0.w;
                C[4]=c1.x; C[5]=c1.y; C[6]=c1.z; C[7]=c1.w;
            } else {
#pragma unroll
                for (int j = 0; j < 8; j++) C[j] = 0.f;
            }
#pragma unroll
            for (int j = 0; j < 8; j++) {
                float s = w1 * A[j] + w4 * B[j] + w7 * C[j];
                if (j > 0) s += w0 * A[j-1] + w3 * B[j-1] + w6 * C[j-1];
                if (j < 7) s += w2 * A[j+1] + w5 * B[j+1] + w8 * C[j+1];
                Ra[(row * 8 + j) * STRK + ch] = __uint_as_float(f2tf32(s));
            }
        }
    }
    __syncthreads();

    // ---- scores via mma.sync: S = q @ k^T per head -> As (Rd) ----
    {
        const uint32_t* Qu = (const uint32_t*)Rb;
        const uint32_t* Ku = (const uint32_t*)Rc;
        float* As = Rd;
        const int gid = lane >> 2, tig = lane & 3;
#pragma unroll
        for (int i = 0; i < 3; i++) {
            int t = wid + 16 * i;
            int head = t >> 3, mt = (t >> 2) & 1, nt = t & 3;
            int bm = head * 32 + mt * 16, bn = head * 32 + nt * 8;
            float dacc[4] = {0.f, 0.f, 0.f, 0.f};
#pragma unroll
            for (int kc = 0; kc < 8; kc++) {
                int kk = kc * 8;
                uint32_t areg[4], breg[2];
                areg[0] = Qu[(bm + gid) * STRC + kk + tig];
                areg[1] = Qu[(bm + gid + 8) * STRC + kk + tig];
                areg[2] = Qu[(bm + gid) * STRC + kk + tig + 4];
                areg[3] = Qu[(bm + gid + 8) * STRC + kk + tig + 4];
                breg[0] = Ku[(bn + gid) * STRC + kk + tig];
                breg[1] = Ku[(bn + gid) * STRC + kk + tig + 4];
                mma16n8k8(dacc, areg, breg);
            }
            float tmp = __ldg(temperature + head);
            float iq0 = Ns[bm + gid] * tmp, iq8 = Ns[bm + gid + 8] * tmp;
            float ik0 = Ns[DIM + bn + 2 * tig], ik1 = Ns[DIM + bn + 2 * tig + 1];
            int dn = nt * 8 + 2 * tig;
            As[(bm + gid) * STRA + dn]         = dacc[0] * iq0 * ik0;
            As[(bm + gid) * STRA + dn + 1]     = dacc[1] * iq0 * ik1;
            As[(bm + gid + 8) * STRA + dn]     = dacc[2] * iq8 * ik0;
            As[(bm + gid + 8) * STRA + dn + 1] = dacc[3] * iq8 * ik1;
        }
    }
    __syncthreads();

    // ---- softmax over d; store tf32-rounded ----
    if (tid < DIM) {
        float* arow = Rd + tid * STRA;
        float m = arow[0];
#pragma unroll
        for (int d = 1; d < 32; d++) m = fmaxf(m, arow[d]);
        float s = 0.f;
        float ev[32];
#pragma unroll
        for (int d = 0; d < 32; d++) { ev[d] = expf(arow[d] - m); s += ev[d]; }
        float inv = 1.f / s;
#pragma unroll
        for (int d = 0; d < 32; d++) arow[d] = __uint_as_float(f2tf32(ev[d] * inv));
    }
    __syncthreads();

    // ---- attn@v via mma.sync: O = A @ V -> Rb tf32 [192][68] ----
    {
        const uint32_t* Au = (const uint32_t*)Rd;
        const uint32_t* Vu = (const uint32_t*)Ra;
        uint32_t* Ou = (uint32_t*)Rb;
        const int gid = lane >> 2, tig = lane & 3;
#pragma unroll
        for (int i = 0; i < 6; i++) {
            int t = wid + 16 * i;
            int head = t >> 4, mt = (t >> 3) & 1, nt = t & 7;
            int bm = head * 32 + mt * 16, bn = nt * 8;
            float dacc[4] = {0.f, 0.f, 0.f, 0.f};
#pragma unroll
            for (int kc = 0; kc < 4; kc++) {
                int kk = kc * 8;
                uint32_t areg[4], breg[2];
                areg[0] = Au[(bm + gid) * STRA + kk + tig];
                areg[1] = Au[(bm + gid + 8) * STRA + kk + tig];
                areg[2] = Au[(bm + gid) * STRA + kk + tig + 4];
                areg[3] = Au[(bm + gid + 8) * STRA + kk + tig + 4];
                breg[0] = Vu[(bn + gid) * STRK + head * 32 + kk + tig];
                breg[1] = Vu[(bn + gid) * STRK + head * 32 + kk + tig + 4];
                mma16n8k8(dacc, areg, breg);
            }
            Ou[(bm + gid) * STRC + bn + 2 * tig]         = f2tf32(dacc[0]);
            Ou[(bm + gid) * STRC + bn + 2 * tig + 1]     = f2tf32(dacc[1]);
            Ou[(bm + gid + 8) * STRC + bn + 2 * tig]     = f2tf32(dacc[2]);
            Ou[(bm + gid + 8) * STRC + bn + 2 * tig + 1] = f2tf32(dacc[3]);
        }
    }
    __syncthreads();

    // ---- proj GEMM via mma.sync tf32, swizzled A staged by cp.async in Ra ----
    {
        const uint32_t* Xu = (const uint32_t*)Rb;
        const int gid = lane >> 2, tig = lane & 3;
        const int mgr = wid >> 2, ngr = wid & 3;
        float dacc[3][2][4];
#pragma unroll
        for (int mt = 0; mt < 3; mt++)
#pragma unroll
            for (int nt = 0; nt < 2; nt++)
#pragma unroll
                for (int q = 0; q < 4; q++) dacc[mt][nt][q] = 0.f;

        for (int e = tid; e < PRJ_CHUNK / 4; e += NTHR)
            cp16(sRa + e * 16, g_projK + e * 4);
        cp_commit();
        cp_wait<0>();
        __syncthreads();

        for (int kc = 0; kc < 12; kc++) {
            const uint32_t sW = sRa + (kc & 1) * PRJ_CHUNK * 4;
            if (kc < 11) {
                uint32_t sN = sRa + ((kc + 1) & 1) * PRJ_CHUNK * 4;
                const uint32_t* src = g_projK + (kc + 1) * PRJ_CHUNK;
                for (int e = tid; e < PRJ_CHUNK / 4; e += NTHR)
                    cp16(sN + e * 16, src + e * 4);
                cp_commit();
            }
#pragma unroll
            for (int ks = 0; ks < 2; ks++) {
                const int kk = ks * 8;
                uint32_t breg[2][2];
#pragma unroll
                for (int nt = 0; nt < 2; nt++) {
                    int col = ngr * 16 + nt * 8 + gid;
                    breg[nt][0] = Xu[(kc * 16 + kk + tig) * STRC + col];
                    breg[nt][1] = Xu[(kc * 16 + kk + tig + 4) * STRC + col];
                }
#pragma unroll
                for (int mt = 0; mt < 3; mt++) {
                    uint32_t areg[4];
                    lds128(areg, sW + (ks * 1536 + (mgr * 3 + mt) * 128 + lane * 4) * 4);
#pragma unroll
                    for (int nt = 0; nt < 2; nt++)
                        mma16n8k8(dacc[mt][nt], areg, breg[nt]);
                }
            }
            if (kc < 11) cp_wait<0>();
            __syncthreads();
        }

        // epilogue: fragments -> gmem with roll(+4,+4)
#pragma unroll
        for (int mt = 0; mt < 3; mt++) {
#pragma unroll
            for (int half = 0; half < 2; half++) {
                int o = mgr * 48 + mt * 16 + gid + half * 8;
                float* obase = out + ((size_t)(bi * DIM + o) * IMG) * IMG;
#pragma unroll
                for (int nt = 0; nt < 2; nt++) {
                    int p = ngr * 16 + nt * 8 + 2 * tig;
                    int i = p >> 3, j = p & 7;
                    int gh = (wh * WSZ + i + SHIFTV) & 255;
                    int gw0 = (ww * WSZ + j + SHIFTV) & 255;
                    int gw1 = (ww * WSZ + j + 1 + SHIFTV) & 255;
                    obase[gh * IMG + gw0] = dacc[mt][nt][half * 2];
                    obase[gh * IMG + gw1] = dacc[mt][nt][half * 2 + 1];
                }
            }
        }
    }
}

extern "C" void kernel_launch(void* const* d_in, const int* in_sizes, int n_in,
                              void* d_out, int out_size) {
    const float* x           = (const float*)d_in[0];
    const float* qkv_w       = (const float*)d_in[1];
    const float* dw_w        = (const float*)d_in[2];
    const float* proj_w      = (const float*)d_in[3];
    const float* temperature = (const float*)d_in[4];
    float* out = (float*)d_out;

    cudaFuncSetAttribute(attn_kernel, cudaFuncAttributeMaxDynamicSharedMemorySize,
                         SMEM_FLOATS * 4);
    wtrans_kernel<<<(640 * DIM + 255) / 256, 256>>>(qkv_w, proj_w);
    attn_kernel<<<4096, NTHR, SMEM_FLOATS * 4>>>(x, dw_w, temperature, out);
}

// round 15
// speedup vs baseline: 1.4582x; 1.0733x over previous
#include <cuda_runtime.h>
#include <cstdint>

#define DIM   192
#define TDIM  576
#define WSZ   8
#define PIX   64
#define IMG   256
#define SHIFTV 4
#define NTHR  512

#define STRC  68
#define STRK  196
#define STRA  33
#define BSW   136    // B-swizzle group stride (banks tig*8+gid*2: conflict-free LDS.64)

#define A_OFF  0      // qkv stage buf0 (10240) -> Vt[64][196] tf32 -> proj stage bufs
#define B_OFF  12544  // X bswz tf32 [96][136] -> Q tf32 [192][68] -> attn-out bswz tf32
#define C_OFF  25600  // qkv stage buf1 (10240) -> K tf32 [192][68]
#define D_OFF  38656  // rawV [192][68] -> As [192][33]
#define NS_OFF 51712  // Ns[0..191] q-norms, [192..383] k-norms
#define SMEM_FLOATS 52160

#define QKV_CHUNK 10240   // words
#define PRJ_CHUNK 3072    // words

typedef unsigned long long ull;

__device__ uint32_t g_qkvK[12 * QKV_CHUNK];   // swizzled tf32 (A fragments lane-ordered)
__device__ uint32_t g_projK[12 * PRJ_CHUNK];

__device__ __forceinline__ uint32_t f2tf32(float f) {
    uint32_t u; asm("cvt.rna.tf32.f32 %0, %1;" : "=r"(u) : "f"(f)); return u;
}

// A-fragment layout (unchanged from R14): block[lane*4 + kh*2 + o8]
__device__ __forceinline__ int swz_idx(int kk16, int o, int ks_stride) {
    int ks = kk16 >> 3, tig = kk16 & 3, kh = (kk16 >> 2) & 1;
    int obase = o >> 4, gid = o & 7, o8 = (o >> 3) & 1;
    return ks * ks_stride + obase * 128 + (gid * 4 + tig) * 4 + kh * 2 + o8;
}

// B-fragment swizzle: element (k-row within tensor c, col p) ->
// ((kc*2+ks)*4+tig)*BSW + p*2 + kh,  where kk16=c&15, ks=kk16>>3, r=kk16&7,
// kh=r>>2, tig=r&3, kc=c>>4
__device__ __forceinline__ int bswz_idx(int c, int p) {
    int kc = c >> 4, kk16 = c & 15;
    int ks = kk16 >> 3, r = kk16 & 7, kh = r >> 2, tg = r & 3;
    return ((kc * 2 + ks) * 4 + tg) * BSW + p * 2 + kh;
}

__global__ void wtrans_kernel(const float* __restrict__ qkv_w,
                              const float* __restrict__ proj_w) {
    int i = blockIdx.x * 256 + threadIdx.x;
    if (i < 640 * DIM) {
        int o = i / DIM, c = i % DIM;
        int chunk = c >> 4, kk16 = c & 15;
        int idx = chunk * QKV_CHUNK + swz_idx(kk16, o, 5120);
        g_qkvK[idx] = (o < TDIM) ? f2tf32(qkv_w[o * DIM + c]) : 0u;
    }
    if (i < DIM * DIM) {
        int o = i / DIM, c = i % DIM;
        int chunk = c >> 4, kk16 = c & 15;
        int idx = chunk * PRJ_CHUNK + swz_idx(kk16, o, 1536);
        g_projK[idx] = f2tf32(proj_w[o * DIM + c]);
    }
}

__device__ __forceinline__ void mma16n8k8(float* d, const uint32_t* a, const uint32_t* b) {
    asm volatile(
        "mma.sync.aligned.m16n8k8.row.col.f32.tf32.tf32.f32 "
        "{%0,%1,%2,%3}, {%4,%5,%6,%7}, {%8,%9}, {%0,%1,%2,%3};"
        : "+f"(d[0]), "+f"(d[1]), "+f"(d[2]), "+f"(d[3])
        : "r"(a[0]), "r"(a[1]), "r"(a[2]), "r"(a[3]), "r"(b[0]), "r"(b[1]));
}
__device__ __forceinline__ uint32_t smem_u32(const void* p) {
    uint32_t a;
    asm("{ .reg .u64 t; cvta.to.shared.u64 t, %1; cvt.u32.u64 %0, t; }" : "=r"(a) : "l"(p));
    return a;
}
__device__ __forceinline__ void cp16(uint32_t saddr, const void* g) {
    asm volatile("cp.async.cg.shared.global [%0], [%1], 16;" :: "r"(saddr), "l"(g));
}
__device__ __forceinline__ void cp_commit() {
    asm volatile("cp.async.commit_group;" ::: "memory");
}
template <int N>
__device__ __forceinline__ void cp_wait() {
    asm volatile("cp.async.wait_group %0;" :: "n"(N) : "memory");
}
__device__ __forceinline__ void lds128(uint32_t* r, uint32_t saddr) {
    asm volatile("ld.shared.v4.b32 {%0,%1,%2,%3}, [%4];"
                 : "=r"(r[0]), "=r"(r[1]), "=r"(r[2]), "=r"(r[3]) : "r"(saddr));
}
__device__ __forceinline__ void lds64(uint32_t* r, uint32_t saddr) {
    asm volatile("ld.shared.v2.b32 {%0,%1}, [%2];"
                 : "=r"(r[0]), "=r"(r[1]) : "r"(saddr));
}

__global__ void __launch_bounds__(NTHR, 1)
attn_kernel(const float* __restrict__ x, const float* __restrict__ dw_w,
            const float* __restrict__ temperature, float* __restrict__ out) {
    extern __shared__ float sm[];
    float* Ra = sm + A_OFF;
    float* Rb = sm + B_OFF;
    float* Rc = sm + C_OFF;
    float* Rd = sm + D_OFF;
    float* Ns = sm + NS_OFF;

    const int tid = threadIdx.x;
    const int win = blockIdx.x;
    const int bi = win >> 10;
    const int wh = (win >> 5) & 31;
    const int ww = win & 31;
    const int lane = tid & 31;
    const int wid = tid >> 5;
    const uint32_t sbase = smem_u32(sm);
    const uint32_t sRa = sbase + A_OFF * 4;
    const uint32_t sRb = sbase + B_OFF * 4;
    const uint32_t sRc = sbase + C_OFF * 4;

    // ---- prefetch qkv chunk 0 FIRST (overlaps window gmem loads) ----
    for (int e = tid; e < QKV_CHUNK / 4; e += NTHR)
        cp16(sRa + e * 16, g_qkvK + e * 4);
    cp_commit();

    // ---- load window with roll(-4,-4) into Rb as B-swizzled tf32 ----
    {
        const float* xb = x + (size_t)bi * DIM * IMG * IMG;
        uint32_t* Xu = (uint32_t*)Rb;
        for (int e = tid; e < DIM * PIX; e += NTHR) {
            int c = e >> 6, p = e & 63;
            int i = p >> 3, j = p & 7;
            int gh = (wh * WSZ + i + SHIFTV) & 255;
            int gw = (ww * WSZ + j + SHIFTV) & 255;
            Xu[bswz_idx(c, p)] = f2tf32(xb[(c * IMG + gh) * IMG + gw]);
        }
    }

    // ---- qkv GEMM via mma.sync tf32 ----
    {
        const uint32_t* Xu = (const uint32_t*)Rb;
        const int gid = lane >> 2, tig = lane & 3;
        const int mg = wid >> 1, ng = wid & 1;
        float dacc[5][4][4];
#pragma unroll
        for (int mt = 0; mt < 5; mt++)
#pragma unroll
            for (int nt = 0; nt < 4; nt++)
#pragma unroll
                for (int q = 0; q < 4; q++) dacc[mt][nt][q] = 0.f;

        cp_wait<0>();
        __syncthreads();

        for (int kc = 0; kc < 12; kc++) {
            const uint32_t sW = (kc & 1) ? sRc : sRa;
            if (kc < 11) {
                uint32_t sN = (kc & 1) ? sRa : sRc;
                const uint32_t* src = g_qkvK + (kc + 1) * QKV_CHUNK;
                for (int e = tid; e < QKV_CHUNK / 4; e += NTHR)
                    cp16(sN + e * 16, src + e * 4);
                cp_commit();
            }
#pragma unroll
            for (int ks = 0; ks < 2; ks++) {
                uint32_t bbase = sRb + (((kc * 2 + ks) * 4 + tig) * BSW) * 4;
                uint32_t breg[4][2];
#pragma unroll
                for (int nt = 0; nt < 4; nt++) {
                    int col = ng * 32 + nt * 8 + gid;
                    lds64(breg[nt], bbase + col * 8);
                }
#pragma unroll
                for (int mt = 0; mt < 5; mt++) {
                    uint32_t areg[4];
                    lds128(areg, sW + (ks * 5120 + (mg * 5 + mt) * 128 + lane * 4) * 4);
#pragma unroll
                    for (int nt = 0; nt < 4; nt++)
                        mma16n8k8(dacc[mt][nt], areg, breg[nt]);
                }
            }
            if (kc < 11) cp_wait<0>();
            __syncthreads();
        }

#pragma unroll
        for (int mt = 0; mt < 5; mt++) {
#pragma unroll
            for (int half = 0; half < 2; half++) {
                int o = mg * 80 + mt * 16 + gid + half * 8;
                if (o < TDIM) {
                    int s = o / DIM, ch = o - s * DIM;
                    float* dst = (s == 0 ? Rb : s == 1 ? Rc : Rd) + ch * STRC + ng * 32 + 2 * tig;
#pragma unroll
                    for (int nt = 0; nt < 4; nt++)
                        *(float2*)(dst + nt * 8) =
                            make_float2(dacc[mt][nt][half * 2], dacc[mt][nt][half * 2 + 1]);
                }
            }
        }
    }
    __syncthreads();

    // ---- dwconv: Q (Rb) and K (Rc) in place with norms; V (Rd) -> Vt (Ra) ----
    {
#pragma unroll
        for (int it = 0; it < 6; it++) {
            int t = it * NTHR + tid;
            int ch_ = t >> 3, row = t & 7;
            int isQ = ch_ < DIM;
            float* rr = (isQ ? Rb : Rc) + (isQ ? ch_ : ch_ - DIM) * STRC;
            const float* wd = dw_w + (size_t)ch_ * 9;
            float w0 = __ldg(wd+0), w1 = __ldg(wd+1), w2 = __ldg(wd+2);
            float w3 = __ldg(wd+3), w4 = __ldg(wd+4), w5 = __ldg(wd+5);
            float w6 = __ldg(wd+6), w7 = __ldg(wd+7), w8 = __ldg(wd+8);
            float A[8], B[8], C[8];
            {
                const float4* r4 = (const float4*)(rr + row * 8);
                float4 b0 = r4[0], b1 = r4[1];
                B[0]=b0.x; B[1]=b0.y; B[2]=b0.z; B[3]=b0.w;
                B[4]=b1.x; B[5]=b1.y; B[6]=b1.z; B[7]=b1.w;
            }
            if (row > 0) {
                const float4* r4 = (const float4*)(rr + (row - 1) * 8);
                float4 a0 = r4[0], a1 = r4[1];
                A[0]=a0.x; A[1]=a0.y; A[2]=a0.z; A[3]=a0.w;
                A[4]=a1.x; A[5]=a1.y; A[6]=a1.z; A[7]=a1.w;
            } else {
#pragma unroll
                for (int j = 0; j < 8; j++) A[j] = 0.f;
            }
            if (row < 7) {
                const float4* r4 = (const float4*)(rr + (row + 1) * 8);
                float4 c0 = r4[0], c1 = r4[1];
                C[0]=c0.x; C[1]=c0.y; C[2]=c0.z; C[3]=c0.w;
                C[4]=c1.x; C[5]=c1.y; C[6]=c1.z; C[7]=c1.w;
            } else {
#pragma unroll
                for (int j = 0; j < 8; j++) C[j] = 0.f;
            }
            float o[8];
            float ss = 0.f;
#pragma unroll
            for (int j = 0; j < 8; j++) {
                float s = w1 * A[j] + w4 * B[j] + w7 * C[j];
                if (j > 0) s += w0 * A[j-1] + w3 * B[j-1] + w6 * C[j-1];
                if (j < 7) s += w2 * A[j+1] + w5 * B[j+1] + w8 * C[j+1];
                o[j] = s;
                ss += s * s;
            }
            ss += __shfl_xor_sync(0xffffffffu, ss, 4);
            ss += __shfl_xor_sync(0xffffffffu, ss, 2);
            ss += __shfl_xor_sync(0xffffffffu, ss, 1);
            __syncwarp();
            float4* w4p = (float4*)(rr + row * 8);
            w4p[0] = make_float4(__uint_as_float(f2tf32(o[0])), __uint_as_float(f2tf32(o[1])),
                                 __uint_as_float(f2tf32(o[2])), __uint_as_float(f2tf32(o[3])));
            w4p[1] = make_float4(__uint_as_float(f2tf32(o[4])), __uint_as_float(f2tf32(o[5])),
                                 __uint_as_float(f2tf32(o[6])), __uint_as_float(f2tf32(o[7])));
            if ((lane & 7) == 0)
                Ns[ch_] = 1.f / fmaxf(sqrtf(ss), 1e-12f);
            __syncwarp();
        }
        // V -> transposed Vt in Ra (tf32)
#pragma unroll
        for (int it = 0; it < 3; it++) {
            int task = it * NTHR + tid;
            int ch = task % DIM;
            int row = task / DIM;
            const float* rr = Rd + ch * STRC;
            const float* wd = dw_w + (size_t)(2 * DIM + ch) * 9;
            float w0 = __ldg(wd+0), w1 = __ldg(wd+1), w2 = __ldg(wd+2);
            float w3 = __ldg(wd+3), w4 = __ldg(wd+4), w5 = __ldg(wd+5);
            float w6 = __ldg(wd+6), w7 = __ldg(wd+7), w8 = __ldg(wd+8);
            float A[8], B[8], C[8];
            {
                const float4* r4 = (const float4*)(rr + row * 8);
                float4 b0 = r4[0], b1 = r4[1];
                B[0]=b0.x; B[1]=b0.y; B[2]=b0.z; B[3]=b0.w;
                B[4]=b1.x; B[5]=b1.y; B[6]=b1.z; B[7]=b1.w;
            }
            if (row > 0) {
                const float4* r4 = (const float4*)(rr + (row - 1) * 8);
                float4 a0 = r4[0], a1 = r4[1];
                A[0]=a0.x; A[1]=a0.y; A[2]=a0.z; A[3]=a0.w;
                A[4]=a1.x; A[5]=a1.y; A[6]=a1.z; A[7]=a1.w;
            } else {
#pragma unroll
                for (int j = 0; j < 8; j++) A[j] = 0.f;
            }
            if (row < 7) {
                const float4* r4 = (const float4*)(rr + (row + 1) * 8);
                float4 c0 = r4[0], c1 = r4[1];
                C[0]=c0.x; C[1]=c0.y; C[2]=c0.z; C[3]=c0.w;
                C[4]=c1.x; C[5]=c1.y; C[6]=c1.z; C[7]=c1.w;
            } else {
#pragma unroll
                for (int j = 0; j < 8; j++) C[j] = 0.f;
            }
#pragma unroll
            for (int j = 0; j < 8; j++) {
                float s = w1 * A[j] + w4 * B[j] + w7 * C[j];
                if (j > 0) s += w0 * A[j-1] + w3 * B[j-1] + w6 * C[j-1];
                if (j < 7) s += w2 * A[j+1] + w5 * B[j+1] + w8 * C[j+1];
                Ra[(row * 8 + j) * STRK + ch] = __uint_as_float(f2tf32(s));
            }
        }
    }
    __syncthreads();

    // ---- scores via mma.sync: S = q @ k^T per head -> As (Rd) ----
    {
        const uint32_t* Qu = (const uint32_t*)Rb;
        const uint32_t* Ku = (const uint32_t*)Rc;
        float* As = Rd;
        const int gid = lane >> 2, tig = lane & 3;
#pragma unroll
        for (int i = 0; i < 3; i++) {
            int t = wid + 16 * i;
            int head = t >> 3, mt = (t >> 2) & 1, nt = t & 3;
            int bm = head * 32 + mt * 16, bn = head * 32 + nt * 8;
            float dacc[4] = {0.f, 0.f, 0.f, 0.f};
#pragma unroll
            for (int kc = 0; kc < 8; kc++) {
                int kk = kc * 8;
                uint32_t areg[4], breg[2];
                areg[0] = Qu[(bm + gid) * STRC + kk + tig];
                areg[1] = Qu[(bm + gid + 8) * STRC + kk + tig];
                areg[2] = Qu[(bm + gid) * STRC + kk + tig + 4];
                areg[3] = Qu[(bm + gid + 8) * STRC + kk + tig + 4];
                breg[0] = Ku[(bn + gid) * STRC + kk + tig];
                breg[1] = Ku[(bn + gid) * STRC + kk + tig + 4];
                mma16n8k8(dacc, areg, breg);
            }
            float tmp = __ldg(temperature + head);
            float iq0 = Ns[bm + gid] * tmp, iq8 = Ns[bm + gid + 8] * tmp;
            float ik0 = Ns[DIM + bn + 2 * tig], ik1 = Ns[DIM + bn + 2 * tig + 1];
            int dn = nt * 8 + 2 * tig;
            As[(bm + gid) * STRA + dn]         = dacc[0] * iq0 * ik0;
            As[(bm + gid) * STRA + dn + 1]     = dacc[1] * iq0 * ik1;
            As[(bm + gid + 8) * STRA + dn]     = dacc[2] * iq8 * ik0;
            As[(bm + gid + 8) * STRA + dn + 1] = dacc[3] * iq8 * ik1;
        }
    }
    __syncthreads();

    // ---- softmax over d; store tf32-rounded ----
    if (tid < DIM) {
        float* arow = Rd + tid * STRA;
        float m = arow[0];
#pragma unroll
        for (int d = 1; d < 32; d++) m = fmaxf(m, arow[d]);
        float s = 0.f;
        float ev[32];
#pragma unroll
        for (int d = 0; d < 32; d++) { ev[d] = expf(arow[d] - m); s += ev[d]; }
        float inv = 1.f / s;
#pragma unroll
        for (int d = 0; d < 32; d++) arow[d] = __uint_as_float(f2tf32(ev[d] * inv));
    }
    __syncthreads();

    // ---- attn@v via mma.sync: O = A @ V -> Rb B-swizzled tf32 ----
    {
        const uint32_t* Au = (const uint32_t*)Rd;
        const uint32_t* Vu = (const uint32_t*)Ra;
        uint32_t* Ou = (uint32_t*)Rb;
        const int gid = lane >> 2, tig = lane & 3;
#pragma unroll
        for (int i = 0; i < 6; i++) {
            int t = wid + 16 * i;
            int head = t >> 4, mt = (t >> 3) & 1, nt = t & 7;
            int bm = head * 32 + mt * 16, bn = nt * 8;
            float dacc[4] = {0.f, 0.f, 0.f, 0.f};
#pragma unroll
            for (int kc = 0; kc < 4; kc++) {
                int kk = kc * 8;
                uint32_t areg[4], breg[2];
                areg[0] = Au[(bm + gid) * STRA + kk + tig];
                areg[1] = Au[(bm + gid + 8) * STRA + kk + tig];
                areg[2] = Au[(bm + gid) * STRA + kk + tig + 4];
                areg[3] = Au[(bm + gid + 8) * STRA + kk + tig + 4];
                breg[0] = Vu[(bn + gid) * STRK + head * 32 + kk + tig];
                breg[1] = Vu[(bn + gid) * STRK + head * 32 + kk + tig + 4];
                mma16n8k8(dacc, areg, breg);
            }
            int px = bn + 2 * tig;
            Ou[bswz_idx(bm + gid, px)]         = f2tf32(dacc[0]);
            Ou[bswz_idx(bm + gid, px + 1)]     = f2tf32(dacc[1]);
            Ou[bswz_idx(bm + gid + 8, px)]     = f2tf32(dacc[2]);
            Ou[bswz_idx(bm + gid + 8, px + 1)] = f2tf32(dacc[3]);
        }
    }
    __syncthreads();

    // ---- proj GEMM via mma.sync tf32, swizzled A staged by cp.async in Ra ----
    {
        const int gid = lane >> 2, tig = lane & 3;
        const int mgr = wid >> 2, ngr = wid & 3;
        float dacc[3][2][4];
#pragma unroll
        for (int mt = 0; mt < 3; mt++)
#pragma unroll
            for (int nt = 0; nt < 2; nt++)
#pragma unroll
                for (int q = 0; q < 4; q++) dacc[mt][nt][q] = 0.f;

        for (int e = tid; e < PRJ_CHUNK / 4; e += NTHR)
            cp16(sRa + e * 16, g_projK + e * 4);
        cp_commit();
        cp_wait<0>();
        __syncthreads();

        for (int kc = 0; kc < 12; kc++) {
            const uint32_t sW = sRa + (kc & 1) * PRJ_CHUNK * 4;
            if (kc < 11) {
                uint32_t sN = sRa + ((kc + 1) & 1) * PRJ_CHUNK * 4;
                const uint32_t* src = g_projK + (kc + 1) * PRJ_CHUNK;
                for (int e = tid; e < PRJ_CHUNK / 4; e += NTHR)
                    cp16(sN + e * 16, src + e * 4);
                cp_commit();
            }
#pragma unroll
            for (int ks = 0; ks < 2; ks++) {
                uint32_t bbase = sRb + (((kc * 2 + ks) * 4 + tig) * BSW) * 4;
                uint32_t breg[2][2];
#pragma unroll
                for (int nt = 0; nt < 2; nt++) {
                    int col = ngr * 16 + nt * 8 + gid;
                    lds64(breg[nt], bbase + col * 8);
                }
#pragma unroll
                for (int mt = 0; mt < 3; mt++) {
                    uint32_t areg[4];
                    lds128(areg, sW + (ks * 1536 + (mgr * 3 + mt) * 128 + lane * 4) * 4);
#pragma unroll
                    for (int nt = 0; nt < 2; nt++)
                        mma16n8k8(dacc[mt][nt], areg, breg[nt]);
                }
            }
            if (kc < 11) cp_wait<0>();
            __syncthreads();
        }

        // epilogue: fragments -> gmem with roll(+4,+4)
#pragma unroll
        for (int mt = 0; mt < 3; mt++) {
#pragma unroll
            for (int half = 0; half < 2; half++) {
                int o = mgr * 48 + mt * 16 + gid + half * 8;
                float* obase = out + ((size_t)(bi * DIM + o) * IMG) * IMG;
#pragma unroll
                for (int nt = 0; nt < 2; nt++) {
                    int p = ngr * 16 + nt * 8 + 2 * tig;
                    int i = p >> 3, j = p & 7;
                    int gh = (wh * WSZ + i + SHIFTV) & 255;
                    int gw0 = (ww * WSZ + j + SHIFTV) & 255;
                    int gw1 = (ww * WSZ + j + 1 + SHIFTV) & 255;
                    obase[gh * IMG + gw0] = dacc[mt][nt][half * 2];
                    obase[gh * IMG + gw1] = dacc[mt][nt][half * 2 + 1];
                }
            }
        }
    }
}

extern "C" void kernel_launch(void* const* d_in, const int* in_sizes, int n_in,
                              void* d_out, int out_size) {
    const float* x           = (const float*)d_in[0];
    const float* qkv_w       = (const float*)d_in[1];
    const float* dw_w        = (const float*)d_in[2];
    const float* proj_w      = (const float*)d_in[3];
    const float* temperature = (const float*)d_in[4];
    float* out = (float*)d_out;

    cudaFuncSetAttribute(attn_kernel, cudaFuncAttributeMaxDynamicSharedMemorySize,
                         SMEM_FLOATS * 4);
    wtrans_kernel<<<(640 * DIM + 255) / 256, 256>>>(qkv_w, proj_w);
    attn_kernel<<<4096, NTHR, SMEM_FLOATS * 4>>>(x, dw_w, temperature, out);
}

// round 16
// speedup vs baseline: 1.5577x; 1.0683x over previous
#include <cuda_runtime.h>
#include <cstdint>

#define DIM   192
#define TDIM  576
#define WSZ   8
#define PIX   64
#define IMG   256
#define SHIFTV 4
#define NTHR  512

#define STRC  72     // Q/K/V-raw channel stride (8*gid+2*tig banks: conflict-free lds64)
#define STRK  196
#define STRA  40     // As row stride (pair layout, conflict-free lds64)
#define BSW   136

#define A_OFF  0      // qkv stage buf0 (10240) -> Vt[64][196] tf32 -> proj stage bufs
#define B_OFF  12544  // X bswz tf32 -> Q tf32 [192][72] -> attn-out bswz tf32
#define C_OFF  26368  // qkv stage buf1 (10240) -> K tf32 [192][72]
#define D_OFF  40192  // rawV [192][72] -> As [192][40] (pair layout)
#define NS_OFF 54016
#define SMEM_FLOATS 54464   // 217856 bytes

#define QKV_CHUNK 10240
#define PRJ_CHUNK 3072

typedef unsigned long long ull;

__device__ uint32_t g_qkvK[12 * QKV_CHUNK];
__device__ uint32_t g_projK[12 * PRJ_CHUNK];

__device__ __forceinline__ uint32_t f2tf32(float f) {
    uint32_t u; asm("cvt.rna.tf32.f32 %0, %1;" : "=r"(u) : "f"(f)); return u;
}

// A-fragment layout: block[lane*4 + kh*2 + o8]
__device__ __forceinline__ int swz_idx(int kk16, int o, int ks_stride) {
    int ks = kk16 >> 3, tig = kk16 & 3, kh = (kk16 >> 2) & 1;
    int obase = o >> 4, gid = o & 7, o8 = (o >> 3) & 1;
    return ks * ks_stride + obase * 128 + (gid * 4 + tig) * 4 + kh * 2 + o8;
}
// B-fragment swizzle for X / attn-out
__device__ __forceinline__ int bswz_idx(int c, int p) {
    int kc = c >> 4, kk16 = c & 15;
    int ks = kk16 >> 3, r = kk16 & 7, kh = r >> 2, tg = r & 3;
    return ((kc * 2 + ks) * 4 + tg) * BSW + p * 2 + kh;
}

__global__ void wtrans_kernel(const float* __restrict__ qkv_w,
                              const float* __restrict__ proj_w) {
    int i = blockIdx.x * 256 + threadIdx.x;
    if (i < 640 * DIM) {
        int o = i / DIM, c = i % DIM;
        int chunk = c >> 4, kk16 = c & 15;
        int idx = chunk * QKV_CHUNK + swz_idx(kk16, o, 5120);
        g_qkvK[idx] = (o < TDIM) ? f2tf32(qkv_w[o * DIM + c]) : 0u;
    }
    if (i < DIM * DIM) {
        int o = i / DIM, c = i % DIM;
        int chunk = c >> 4, kk16 = c & 15;
        int idx = chunk * PRJ_CHUNK + swz_idx(kk16, o, 1536);
        g_projK[idx] = f2tf32(proj_w[o * DIM + c]);
    }
}

__device__ __forceinline__ void mma16n8k8(float* d, const uint32_t* a, const uint32_t* b) {
    asm volatile(
        "mma.sync.aligned.m16n8k8.row.col.f32.tf32.tf32.f32 "
        "{%0,%1,%2,%3}, {%4,%5,%6,%7}, {%8,%9}, {%0,%1,%2,%3};"
        : "+f"(d[0]), "+f"(d[1]), "+f"(d[2]), "+f"(d[3])
        : "r"(a[0]), "r"(a[1]), "r"(a[2]), "r"(a[3]), "r"(b[0]), "r"(b[1]));
}
__device__ __forceinline__ uint32_t smem_u32(const void* p) {
    uint32_t a;
    asm("{ .reg .u64 t; cvta.to.shared.u64 t, %1; cvt.u32.u64 %0, t; }" : "=r"(a) : "l"(p));
    return a;
}
__device__ __forceinline__ void cp16(uint32_t saddr, const void* g) {
    asm volatile("cp.async.cg.shared.global [%0], [%1], 16;" :: "r"(saddr), "l"(g));
}
__device__ __forceinline__ void cp_commit() {
    asm volatile("cp.async.commit_group;" ::: "memory");
}
template <int N>
__device__ __forceinline__ void cp_wait() {
    asm volatile("cp.async.wait_group %0;" :: "n"(N) : "memory");
}
__device__ __forceinline__ void lds128(uint32_t* r, uint32_t saddr) {
    asm volatile("ld.shared.v4.b32 {%0,%1,%2,%3}, [%4];"
                 : "=r"(r[0]), "=r"(r[1]), "=r"(r[2]), "=r"(r[3]) : "r"(saddr));
}
__device__ __forceinline__ void lds64(uint32_t* r, uint32_t saddr) {
    asm volatile("ld.shared.v2.b32 {%0,%1}, [%2];"
                 : "=r"(r[0]), "=r"(r[1]) : "r"(saddr));
}

__global__ void __launch_bounds__(NTHR, 1)
attn_kernel(const float* __restrict__ x, const float* __restrict__ dw_w,
            const float* __restrict__ temperature, float* __restrict__ out) {
    extern __shared__ float sm[];
    float* Ra = sm + A_OFF;
    float* Rb = sm + B_OFF;
    float* Rc = sm + C_OFF;
    float* Rd = sm + D_OFF;
    float* Ns = sm + NS_OFF;

    const int tid = threadIdx.x;
    const int win = blockIdx.x;
    const int bi = win >> 10;
    const int wh = (win >> 5) & 31;
    const int ww = win & 31;
    const int lane = tid & 31;
    const int wid = tid >> 5;
    const uint32_t sbase = smem_u32(sm);
    const uint32_t sRa = sbase + A_OFF * 4;
    const uint32_t sRb = sbase + B_OFF * 4;
    const uint32_t sRc = sbase + C_OFF * 4;
    const uint32_t sRd = sbase + D_OFF * 4;

    // ---- prefetch qkv chunk 0 FIRST (overlaps window gmem loads) ----
    for (int e = tid; e < QKV_CHUNK / 4; e += NTHR)
        cp16(sRa + e * 16, g_qkvK + e * 4);
    cp_commit();

    // ---- load window with roll(-4,-4) into Rb as B-swizzled tf32 ----
    {
        const float* xb = x + (size_t)bi * DIM * IMG * IMG;
        uint32_t* Xu = (uint32_t*)Rb;
        for (int e = tid; e < DIM * PIX; e += NTHR) {
            int c = e >> 6, p = e & 63;
            int i = p >> 3, j = p & 7;
            int gh = (wh * WSZ + i + SHIFTV) & 255;
            int gw = (ww * WSZ + j + SHIFTV) & 255;
            Xu[bswz_idx(c, p)] = f2tf32(xb[(c * IMG + gh) * IMG + gw]);
        }
    }

    // ---- qkv GEMM via mma.sync tf32 ----
    {
        const int gid = lane >> 2, tig = lane & 3;
        const int mg = wid >> 1, ng = wid & 1;
        float dacc[5][4][4];
#pragma unroll
        for (int mt = 0; mt < 5; mt++)
#pragma unroll
            for (int nt = 0; nt < 4; nt++)
#pragma unroll
                for (int q = 0; q < 4; q++) dacc[mt][nt][q] = 0.f;

        cp_wait<0>();
        __syncthreads();

        for (int kc = 0; kc < 12; kc++) {
            const uint32_t sW = (kc & 1) ? sRc : sRa;
            if (kc < 11) {
                uint32_t sN = (kc & 1) ? sRa : sRc;
                const uint32_t* src = g_qkvK + (kc + 1) * QKV_CHUNK;
                for (int e = tid; e < QKV_CHUNK / 4; e += NTHR)
                    cp16(sN + e * 16, src + e * 4);
                cp_commit();
            }
#pragma unroll
            for (int ks = 0; ks < 2; ks++) {
                uint32_t bbase = sRb + (((kc * 2 + ks) * 4 + tig) * BSW) * 4;
                uint32_t breg[4][2];
#pragma unroll
                for (int nt = 0; nt < 4; nt++) {
                    int col = ng * 32 + nt * 8 + gid;
                    lds64(breg[nt], bbase + col * 8);
                }
#pragma unroll
                for (int mt = 0; mt < 5; mt++) {
                    uint32_t areg[4];
                    lds128(areg, sW + (ks * 5120 + (mg * 5 + mt) * 128 + lane * 4) * 4);
#pragma unroll
                    for (int nt = 0; nt < 4; nt++)
                        mma16n8k8(dacc[mt][nt], areg, breg[nt]);
                }
            }
            if (kc < 11) cp_wait<0>();
            __syncthreads();
        }

#pragma unroll
        for (int mt = 0; mt < 5; mt++) {
#pragma unroll
            for (int half = 0; half < 2; half++) {
                int o = mg * 80 + mt * 16 + gid + half * 8;
                if (o < TDIM) {
                    int s = o / DIM, ch = o - s * DIM;
                    float* dst = (s == 0 ? Rb : s == 1 ? Rc : Rd) + ch * STRC + ng * 32 + 2 * tig;
#pragma unroll
                    for (int nt = 0; nt < 4; nt++)
                        *(float2*)(dst + nt * 8) =
                            make_float2(dacc[mt][nt][half * 2], dacc[mt][nt][half * 2 + 1]);
                }
            }
        }
    }
    __syncthreads();

    // ---- dwconv: Q (Rb), K (Rc) in place (PAIR-PERMUTED stores) + norms;
    //      V (Rd) -> Vt (Ra) ----
    {
#pragma unroll
        for (int it = 0; it < 6; it++) {
            int t = it * NTHR + tid;
            int ch_ = t >> 3, row = t & 7;
            int isQ = ch_ < DIM;
            float* rr = (isQ ? Rb : Rc) + (isQ ? ch_ : ch_ - DIM) * STRC;
            const float* wd = dw_w + (size_t)ch_ * 9;
            float w0 = __ldg(wd+0), w1 = __ldg(wd+1), w2 = __ldg(wd+2);
            float w3 = __ldg(wd+3), w4 = __ldg(wd+4), w5 = __ldg(wd+5);
            float w6 = __ldg(wd+6), w7 = __ldg(wd+7), w8 = __ldg(wd+8);
            float A[8], B[8], C[8];
            {
                const float4* r4 = (const float4*)(rr + row * 8);
                float4 b0 = r4[0], b1 = r4[1];
                B[0]=b0.x; B[1]=b0.y; B[2]=b0.z; B[3]=b0.w;
                B[4]=b1.x; B[5]=b1.y; B[6]=b1.z; B[7]=b1.w;
            }
            if (row > 0) {
                const float4* r4 = (const float4*)(rr + (row - 1) * 8);
                float4 a0 = r4[0], a1 = r4[1];
                A[0]=a0.x; A[1]=a0.y; A[2]=a0.z; A[3]=a0.w;
                A[4]=a1.x; A[5]=a1.y; A[6]=a1.z; A[7]=a1.w;
            } else {
#pragma unroll
                for (int j = 0; j < 8; j++) A[j] = 0.f;
            }
            if (row < 7) {
                const float4* r4 = (const float4*)(rr + (row + 1) * 8);
                float4 c0 = r4[0], c1 = r4[1];
                C[0]=c0.x; C[1]=c0.y; C[2]=c0.z; C[3]=c0.w;
                C[4]=c1.x; C[5]=c1.y; C[6]=c1.z; C[7]=c1.w;
            } else {
#pragma unroll
                for (int j = 0; j < 8; j++) C[j] = 0.f;
            }
            float o[8];
            float ss = 0.f;
#pragma unroll
            for (int j = 0; j < 8; j++) {
                float s = w1 * A[j] + w4 * B[j] + w7 * C[j];
                if (j > 0) s += w0 * A[j-1] + w3 * B[j-1] + w6 * C[j-1];
                if (j < 7) s += w2 * A[j+1] + w5 * B[j+1] + w8 * C[j+1];
                o[j] = s;
                ss += s * s;
            }
            ss += __shfl_xor_sync(0xffffffffu, ss, 4);
            ss += __shfl_xor_sync(0xffffffffu, ss, 2);
            ss += __shfl_xor_sync(0xffffffffu, ss, 1);
            __syncwarp();
            // pair-permuted store: pixel 8r+j -> 8r + (j&3)*2 + (j>>2)
            float4* w4p = (float4*)(rr + row * 8);
            w4p[0] = make_float4(__uint_as_float(f2tf32(o[0])), __uint_as_float(f2tf32(o[4])),
                                 __uint_as_float(f2tf32(o[1])), __uint_as_float(f2tf32(o[5])));
            w4p[1] = make_float4(__uint_as_float(f2tf32(o[2])), __uint_as_float(f2tf32(o[6])),
                                 __uint_as_float(f2tf32(o[3])), __uint_as_float(f2tf32(o[7])));
            if ((lane & 7) == 0)
                Ns[ch_] = 1.f / fmaxf(sqrtf(ss), 1e-12f);
            __syncwarp();
        }
        // V -> transposed Vt in Ra (tf32), layout unchanged
#pragma unroll
        for (int it = 0; it < 3; it++) {
            int task = it * NTHR + tid;
            int ch = task % DIM;
            int row = task / DIM;
            const float* rr = Rd + ch * STRC;
            const float* wd = dw_w + (size_t)(2 * DIM + ch) * 9;
            float w0 = __ldg(wd+0), w1 = __ldg(wd+1), w2 = __ldg(wd+2);
            float w3 = __ldg(wd+3), w4 = __ldg(wd+4), w5 = __ldg(wd+5);
            float w6 = __ldg(wd+6), w7 = __ldg(wd+7), w8 = __ldg(wd+8);
            float A[8], B[8], C[8];
            {
                const float4* r4 = (const float4*)(rr + row * 8);
                float4 b0 = r4[0], b1 = r4[1];
                B[0]=b0.x; B[1]=b0.y; B[2]=b0.z; B[3]=b0.w;
                B[4]=b1.x; B[5]=b1.y; B[6]=b1.z; B[7]=b1.w;
            }
            if (row > 0) {
                const float4* r4 = (const float4*)(rr + (row - 1) * 8);
                float4 a0 = r4[0], a1 = r4[1];
                A[0]=a0.x; A[1]=a0.y; A[2]=a0.z; A[3]=a0.w;
                A[4]=a1.x; A[5]=a1.y; A[6]=a1.z; A[7]=a1.w;
            } else {
#pragma unroll
                for (int j = 0; j < 8; j++) A[j] = 0.f;
            }
            if (row < 7) {
                const float4* r4 = (const float4*)(rr + (row + 1) * 8);
                float4 c0 = r4[0], c1 = r4[1];
                C[0]=c0.x; C[1]=c0.y; C[2]=c0.z; C[3]=c0.w;
                C[4]=c1.x; C[5]=c1.y; C[6]=c1.z; C[7]=c1.w;
            } else {
#pragma unroll
                for (int j = 0; j < 8; j++) C[j] = 0.f;
            }
#pragma unroll
            for (int j = 0; j < 8; j++) {
                float s = w1 * A[j] + w4 * B[j] + w7 * C[j];
                if (j > 0) s += w0 * A[j-1] + w3 * B[j-1] + w6 * C[j-1];
                if (j < 7) s += w2 * A[j+1] + w5 * B[j+1] + w8 * C[j+1];
                Ra[(row * 8 + j) * STRK + ch] = __uint_as_float(f2tf32(s));
            }
        }
    }
    __syncthreads();

    // ---- scores via mma.sync (pair lds64 fragments): S -> As (Rd, pair layout) ----
    {
        float* As = Rd;
        const int gid = lane >> 2, tig = lane & 3;
#pragma unroll
        for (int i = 0; i < 3; i++) {
            int t = wid + 16 * i;
            int head = t >> 3, mt = (t >> 2) & 1, nt = t & 3;
            int bm = head * 32 + mt * 16, bn = head * 32 + nt * 8;
            float dacc[4] = {0.f, 0.f, 0.f, 0.f};
#pragma unroll
            for (int kc = 0; kc < 8; kc++) {
                uint32_t p0[2], p1[2], pb[2];
                uint32_t cofs = (kc * 8 + tig * 2) * 4;
                lds64(p0, sRb + ((bm + gid) * STRC) * 4 + cofs);
                lds64(p1, sRb + ((bm + gid + 8) * STRC) * 4 + cofs);
                lds64(pb, sRc + ((bn + gid) * STRC) * 4 + cofs);
                uint32_t areg[4] = {p0[0], p1[0], p0[1], p1[1]};
                mma16n8k8(dacc, areg, pb);
            }
            float tmp = __ldg(temperature + head);
            float iq0 = Ns[bm + gid] * tmp, iq8 = Ns[bm + gid + 8] * tmp;
            float ik0 = Ns[DIM + bn + 2 * tig], ik1 = Ns[DIM + bn + 2 * tig + 1];
            // store into pair layout: logical d -> 8*(d>>3) + (d&3)*2 + ((d>>2)&1)
            int d0 = 2 * tig, d1 = 2 * tig + 1;
            int p0o = nt * 8 + (d0 & 3) * 2 + ((d0 >> 2) & 1);
            int p1o = nt * 8 + (d1 & 3) * 2 + ((d1 >> 2) & 1);
            As[(bm + gid) * STRA + p0o]     = dacc[0] * iq0 * ik0;
            As[(bm + gid) * STRA + p1o]     = dacc[1] * iq0 * ik1;
            As[(bm + gid + 8) * STRA + p0o] = dacc[2] * iq8 * ik0;
            As[(bm + gid + 8) * STRA + p1o] = dacc[3] * iq8 * ik1;
        }
    }
    __syncthreads();

    // ---- softmax over row (order-invariant under pair permutation) ----
    if (tid < DIM) {
        float* arow = Rd + tid * STRA;
        float m = arow[0];
#pragma unroll
        for (int d = 1; d < 32; d++) m = fmaxf(m, arow[d]);
        float s = 0.f;
        float ev[32];
#pragma unroll
        for (int d = 0; d < 32; d++) { ev[d] = expf(arow[d] - m); s += ev[d]; }
        float inv = 1.f / s;
#pragma unroll
        for (int d = 0; d < 32; d++) arow[d] = __uint_as_float(f2tf32(ev[d] * inv));
    }
    __syncthreads();

    // ---- attn@v via mma.sync (A pairs via lds64): O -> Rb B-swizzled tf32 ----
    {
        const uint32_t* Vu = (const uint32_t*)Ra;
        uint32_t* Ou = (uint32_t*)Rb;
        const int gid = lane >> 2, tig = lane & 3;
#pragma unroll
        for (int i = 0; i < 6; i++) {
            int t = wid + 16 * i;
            int head = t >> 4, mt = (t >> 3) & 1, nt = t & 7;
            int bm = head * 32 + mt * 16, bn = nt * 8;
            float dacc[4] = {0.f, 0.f, 0.f, 0.f};
#pragma unroll
            for (int kc = 0; kc < 4; kc++) {
                int kk = kc * 8;
                uint32_t p0[2], p1[2], breg[2];
                uint32_t cofs = (kk + tig * 2) * 4;
                lds64(p0, sRd + ((bm + gid) * STRA) * 4 + cofs);
                lds64(p1, sRd + ((bm + gid + 8) * STRA) * 4 + cofs);
                breg[0] = Vu[(bn + gid) * STRK + head * 32 + kk + tig];
                breg[1] = Vu[(bn + gid) * STRK + head * 32 + kk + tig + 4];
                uint32_t areg[4] = {p0[0], p1[0], p0[1], p1[1]};
                mma16n8k8(dacc, areg, breg);
            }
            int px = bn + 2 * tig;
            Ou[bswz_idx(bm + gid, px)]         = f2tf32(dacc[0]);
            Ou[bswz_idx(bm + gid, px + 1)]     = f2tf32(dacc[1]);
            Ou[bswz_idx(bm + gid + 8, px)]     = f2tf32(dacc[2]);
            Ou[bswz_idx(bm + gid + 8, px + 1)] = f2tf32(dacc[3]);
        }
    }
    __syncthreads();

    // ---- proj GEMM via mma.sync tf32, swizzled A staged by cp.async in Ra ----
    {
        const int gid = lane >> 2, tig = lane & 3;
        const int mgr = wid >> 2, ngr = wid & 3;
        float dacc[3][2][4];
#pragma unroll
        for (int mt = 0; mt < 3; mt++)
#pragma unroll
            for (int nt = 0; nt < 2; nt++)
#pragma unroll
                for (int q = 0; q < 4; q++) dacc[mt][nt][q] = 0.f;

        for (int e = tid; e < PRJ_CHUNK / 4; e += NTHR)
            cp16(sRa + e * 16, g_projK + e * 4);
        cp_commit();
        cp_wait<0>();
        __syncthreads();

        for (int kc = 0; kc < 12; kc++) {
            const uint32_t sW = sRa + (kc & 1) * PRJ_CHUNK * 4;
            if (kc < 11) {
                uint32_t sN = sRa + ((kc + 1) & 1) * PRJ_CHUNK * 4;
                const uint32_t* src = g_projK + (kc + 1) * PRJ_CHUNK;
                for (int e = tid; e < PRJ_CHUNK / 4; e += NTHR)
                    cp16(sN + e * 16, src + e * 4);
                cp_commit();
            }
#pragma unroll
            for (int ks = 0; ks < 2; ks++) {
                uint32_t bbase = sRb + (((kc * 2 + ks) * 4 + tig) * BSW) * 4;
                uint32_t breg[2][2];
#pragma unroll
                for (int nt = 0; nt < 2; nt++) {
                    int col = ngr * 16 + nt * 8 + gid;
                    lds64(breg[nt], bbase + col * 8);
                }
#pragma unroll
                for (int mt = 0; mt < 3; mt++) {
                    uint32_t areg[4];
                    lds128(areg, sW + (ks * 1536 + (mgr * 3 + mt) * 128 + lane * 4) * 4);
#pragma unroll
                    for (int nt = 0; nt < 2; nt++)
                        mma16n8k8(dacc[mt][nt], areg, breg[nt]);
                }
            }
            if (kc < 11) cp_wait<0>();
            __syncthreads();
        }

        // epilogue: fragments -> gmem with roll(+4,+4)
#pragma unroll
        for (int mt = 0; mt < 3; mt++) {
#pragma unroll
            for (int half = 0; half < 2; half++) {
                int o = mgr * 48 + mt * 16 + gid + half * 8;
                float* obase = out + ((size_t)(bi * DIM + o) * IMG) * IMG;
#pragma unroll
                for (int nt = 0; nt < 2; nt++) {
                    int p = ngr * 16 + nt * 8 + 2 * tig;
                    int i = p >> 3, j = p & 7;
                    int gh = (wh * WSZ + i + SHIFTV) & 255;
                    int gw0 = (ww * WSZ + j + SHIFTV) & 255;
                    int gw1 = (ww * WSZ + j + 1 + SHIFTV) & 255;
                    obase[gh * IMG + gw0] = dacc[mt][nt][half * 2];
                    obase[gh * IMG + gw1] = dacc[mt][nt][half * 2 + 1];
                }
            }
        }
    }
}

extern "C" void kernel_launch(void* const* d_in, const int* in_sizes, int n_in,
                              void* d_out, int out_size) {
    const float* x           = (const float*)d_in[0];
    const float* qkv_w       = (const float*)d_in[1];
    const float* dw_w        = (const float*)d_in[2];
    const float* proj_w      = (const float*)d_in[3];
    const float* temperature = (const float*)d_in[4];
    float* out = (float*)d_out;

    cudaFuncSetAttribute(attn_kernel, cudaFuncAttributeMaxDynamicSharedMemorySize,
                         SMEM_FLOATS * 4);
    wtrans_kernel<<<(640 * DIM + 255) / 256, 256>>>(qkv_w, proj_w);
    attn_kernel<<<4096, NTHR, SMEM_FLOATS * 4>>>(x, dw_w, temperature, out);
}

// round 17
// speedup vs baseline: 1.6327x; 1.0481x over previous
#include <cuda_runtime.h>
#include <cstdint>

#define DIM   192
#define TDIM  576
#define WSZ   8
#define PIX   64
#define IMG   256
#define SHIFTV 4
#define NTHR  512

#define STRC  72
#define STRK  196
#define STRA  40
#define BSW   136

#define A_OFF  0      // qkv stage buf / Vt[64][196] / proj stage bufs
#define B_OFF  12544  // X bswz tf32 -> Q tf32 [192][72] -> attn-out bswz tf32
#define C_OFF  26368  // qkv stage buf -> K tf32 [192][72]
#define D_OFF  40192  // qkv stage buf -> rawV [192][72] -> As [192][40]
#define NS_OFF 54016
#define SMEM_FLOATS 54464

#define QKV_CHUNK 10240
#define PRJ_CHUNK 3072

typedef unsigned long long ull;

__device__ uint32_t g_qkvK[12 * QKV_CHUNK];
__device__ uint32_t g_projK[12 * PRJ_CHUNK];

__device__ __forceinline__ uint32_t f2tf32(float f) {
    uint32_t u; asm("cvt.rna.tf32.f32 %0, %1;" : "=r"(u) : "f"(f)); return u;
}
__device__ __forceinline__ int swz_idx(int kk16, int o, int ks_stride) {
    int ks = kk16 >> 3, tig = kk16 & 3, kh = (kk16 >> 2) & 1;
    int obase = o >> 4, gid = o & 7, o8 = (o >> 3) & 1;
    return ks * ks_stride + obase * 128 + (gid * 4 + tig) * 4 + kh * 2 + o8;
}
__device__ __forceinline__ int bswz_idx(int c, int p) {
    int kc = c >> 4, kk16 = c & 15;
    int ks = kk16 >> 3, r = kk16 & 7, kh = r >> 2, tg = r & 3;
    return ((kc * 2 + ks) * 4 + tg) * BSW + p * 2 + kh;
}

__global__ void wtrans_kernel(const float* __restrict__ qkv_w,
                              const float* __restrict__ proj_w) {
    int i = blockIdx.x * 256 + threadIdx.x;
    if (i < 640 * DIM) {
        int o = i / DIM, c = i % DIM;
        int chunk = c >> 4, kk16 = c & 15;
        g_qkvK[chunk * QKV_CHUNK + swz_idx(kk16, o, 5120)] =
            (o < TDIM) ? f2tf32(qkv_w[o * DIM + c]) : 0u;
    }
    if (i < DIM * DIM) {
        int o = i / DIM, c = i % DIM;
        int chunk = c >> 4, kk16 = c & 15;
        g_projK[chunk * PRJ_CHUNK + swz_idx(kk16, o, 1536)] = f2tf32(proj_w[o * DIM + c]);
    }
}

__device__ __forceinline__ void mma16n8k8(float* d, const uint32_t* a, const uint32_t* b) {
    asm volatile(
        "mma.sync.aligned.m16n8k8.row.col.f32.tf32.tf32.f32 "
        "{%0,%1,%2,%3}, {%4,%5,%6,%7}, {%8,%9}, {%0,%1,%2,%3};"
        : "+f"(d[0]), "+f"(d[1]), "+f"(d[2]), "+f"(d[3])
        : "r"(a[0]), "r"(a[1]), "r"(a[2]), "r"(a[3]), "r"(b[0]), "r"(b[1]));
}
__device__ __forceinline__ uint32_t smem_u32(const void* p) {
    uint32_t a;
    asm("{ .reg .u64 t; cvta.to.shared.u64 t, %1; cvt.u32.u64 %0, t; }" : "=r"(a) : "l"(p));
    return a;
}
__device__ __forceinline__ void cp16(uint32_t saddr, const void* g) {
    asm volatile("cp.async.cg.shared.global [%0], [%1], 16;" :: "r"(saddr), "l"(g));
}
__device__ __forceinline__ void cp_commit() {
    asm volatile("cp.async.commit_group;" ::: "memory");
}
template <int N>
__device__ __forceinline__ void cp_wait() {
    asm volatile("cp.async.wait_group %0;" :: "n"(N) : "memory");
}
__device__ __forceinline__ void lds128(uint32_t* r, uint32_t saddr) {
    asm volatile("ld.shared.v4.b32 {%0,%1,%2,%3}, [%4];"
                 : "=r"(r[0]), "=r"(r[1]), "=r"(r[2]), "=r"(r[3]) : "r"(saddr));
}
__device__ __forceinline__ void lds64(uint32_t* r, uint32_t saddr) {
    asm volatile("ld.shared.v2.b32 {%0,%1}, [%2];"
                 : "=r"(r[0]), "=r"(r[1]) : "r"(saddr));
}
__device__ __forceinline__ ull dup2(float v) {
    ull r; asm("mov.b64 %0, {%1, %1};" : "=l"(r) : "f"(v)); return r;
}
__device__ __forceinline__ ull pack2(float lo, float hi) {
    ull r; asm("mov.b64 %0, {%1, %2};" : "=l"(r) : "f"(lo), "f"(hi)); return r;
}
__device__ __forceinline__ void ffma2(ull& d, ull a, ull b) {
    asm("fma.rn.f32x2 %0, %1, %2, %0;" : "+l"(d) : "l"(a), "l"(b));
}
__device__ __forceinline__ float2 ull2f2(ull v) {
    float2 r; asm("mov.b64 {%0, %1}, %2;" : "=f"(r.x), "=f"(r.y) : "l"(v)); return r;
}

// load one row of 8 (or zeros) from rr
__device__ __forceinline__ void ldrow(const float* rr, int valid, float* X) {
    if (valid) {
        const float4* r4 = (const float4*)rr;
        float4 a = r4[0], b = r4[1];
        X[0]=a.x; X[1]=a.y; X[2]=a.z; X[3]=a.w;
        X[4]=b.x; X[5]=b.y; X[6]=b.z; X[7]=b.w;
    } else {
#pragma unroll
        for (int j = 0; j < 8; j++) X[j] = 0.f;
    }
}
// 6 pair-packs of a row: t=-1..4 -> (X[t], X[t+4]) with OOB=0
__device__ __forceinline__ void mkpairs(const float* X, ull* P) {
    P[0] = pack2(0.f, X[3]);
    P[1] = pack2(X[0], X[4]);
    P[2] = pack2(X[1], X[5]);
    P[3] = pack2(X[2], X[6]);
    P[4] = pack2(X[3], X[7]);
    P[5] = pack2(X[4], 0.f);
}

__global__ void __launch_bounds__(NTHR, 1)
attn_kernel(const float* __restrict__ x, const float* __restrict__ dw_w,
            const float* __restrict__ temperature, float* __restrict__ out) {
    extern __shared__ float sm[];
    float* Ra = sm + A_OFF;
    float* Rb = sm + B_OFF;
    float* Rc = sm + C_OFF;
    float* Rd = sm + D_OFF;
    float* Ns = sm + NS_OFF;

    const int tid = threadIdx.x;
    const int win = blockIdx.x;
    const int bi = win >> 10;
    const int wh = (win >> 5) & 31;
    const int ww = win & 31;
    const int lane = tid & 31;
    const int wid = tid >> 5;
    const uint32_t sbase = smem_u32(sm);
    const uint32_t sRa = sbase + A_OFF * 4;
    const uint32_t sRb = sbase + B_OFF * 4;
    const uint32_t sRc = sbase + C_OFF * 4;
    const uint32_t sRd = sbase + D_OFF * 4;

    // ---- prefetch qkv chunks 0,1 (triple-buffer ring Ra/Rc/Rd) ----
    {
        for (int e = tid; e < QKV_CHUNK / 4; e += NTHR)
            cp16(sRa + e * 16, g_qkvK + e * 4);
        cp_commit();
        for (int e = tid; e < QKV_CHUNK / 4; e += NTHR)
            cp16(sRc + e * 16, g_qkvK + QKV_CHUNK + e * 4);
        cp_commit();
    }

    // ---- load window with roll(-4,-4) into Rb as B-swizzled tf32 ----
    {
        const float* xb = x + (size_t)bi * DIM * IMG * IMG;
        uint32_t* Xu = (uint32_t*)Rb;
        int p = tid & 63, cb = tid >> 6;
        int i = p >> 3, j = p & 7;
        int gh = (wh * WSZ + i + SHIFTV) & 255;
        int gw = (ww * WSZ + j + SHIFTV) & 255;
        const float* src = xb + gh * IMG + gw;
#pragma unroll 4
        for (int cc = 0; cc < 24; cc++) {
            int c = cb + cc * 8;
            Xu[bswz_idx(c, p)] = f2tf32(src[(size_t)c * IMG * IMG]);
        }
    }

    // ---- qkv GEMM via mma.sync tf32, triple-buffered cp.async staging ----
    {
        const int gid = lane >> 2, tig = lane & 3;
        const int mg = wid >> 1, ng = wid & 1;
        const uint32_t bufs[3] = {sRa, sRc, sRd};
        float dacc[5][4][4];
#pragma unroll
        for (int mt = 0; mt < 5; mt++)
#pragma unroll
            for (int nt = 0; nt < 4; nt++)
#pragma unroll
                for (int q = 0; q < 4; q++) dacc[mt][nt][q] = 0.f;

        for (int kc = 0; kc < 12; kc++) {
            if (kc < 11) cp_wait<1>(); else cp_wait<0>();
            __syncthreads();
            if (kc + 2 < 12) {
                uint32_t sN = bufs[(kc + 2) % 3];
                const uint32_t* src = g_qkvK + (kc + 2) * QKV_CHUNK;
                for (int e = tid; e < QKV_CHUNK / 4; e += NTHR)
                    cp16(sN + e * 16, src + e * 4);
                cp_commit();
            }
            const uint32_t sW = bufs[kc % 3];
#pragma unroll
            for (int ks = 0; ks < 2; ks++) {
                uint32_t bbase = sRb + (((kc * 2 + ks) * 4 + tig) * BSW) * 4;
                uint32_t breg[4][2];
#pragma unroll
                for (int nt = 0; nt < 4; nt++) {
                    int col = ng * 32 + nt * 8 + gid;
                    lds64(breg[nt], bbase + col * 8);
                }
#pragma unroll
                for (int mt = 0; mt < 5; mt++) {
                    uint32_t areg[4];
                    lds128(areg, sW + (ks * 5120 + (mg * 5 + mt) * 128 + lane * 4) * 4);
#pragma unroll
                    for (int nt = 0; nt < 4; nt++)
                        mma16n8k8(dacc[mt][nt], areg, breg[nt]);
                }
            }
        }
        __syncthreads();   // all MMAs done before q/k/v overwrite staging/X

#pragma unroll
        for (int mt = 0; mt < 5; mt++) {
#pragma unroll
            for (int half = 0; half < 2; half++) {
                int o = mg * 80 + mt * 16 + gid + half * 8;
                if (o < TDIM) {
                    int s = o / DIM, ch = o - s * DIM;
                    float* dst = (s == 0 ? Rb : s == 1 ? Rc : Rd) + ch * STRC + ng * 32 + 2 * tig;
#pragma unroll
                    for (int nt = 0; nt < 4; nt++)
                        *(float2*)(dst + nt * 8) =
                            make_float2(dacc[mt][nt][half * 2], dacc[mt][nt][half * 2 + 1]);
                }
            }
        }
    }
    __syncthreads();

    // ---- dwconv (f32x2 pairs): Q (Rb), K (Rc) in place pair-permuted + norms;
    //      V (Rd) -> Vt (Ra) ----
    {
#pragma unroll
        for (int it = 0; it < 6; it++) {
            int t = it * NTHR + tid;
            int ch_ = t >> 3, row = t & 7;
            int isQ = ch_ < DIM;
            float* rr = (isQ ? Rb : Rc) + (isQ ? ch_ : ch_ - DIM) * STRC;
            const float* wd = dw_w + (size_t)ch_ * 9;
            ull wdp[9];
#pragma unroll
            for (int u = 0; u < 9; u++) wdp[u] = dup2(__ldg(wd + u));
            float A[8], B[8], C[8];
            ldrow(rr + row * 8, 1, B);
            ldrow(rr + (row - 1) * 8, row > 0, A);
            ldrow(rr + (row + 1) * 8, row < 7, C);
            ull pA[6], pB[6], pC[6];
            mkpairs(A, pA); mkpairs(B, pB); mkpairs(C, pC);
            ull o2[4];
            ull ssp = 0ull;
#pragma unroll
            for (int j = 0; j < 4; j++) {
                ull acc = 0ull;
                ffma2(acc, pA[j], wdp[0]); ffma2(acc, pA[j + 1], wdp[1]); ffma2(acc, pA[j + 2], wdp[2]);
                ffma2(acc, pB[j], wdp[3]); ffma2(acc, pB[j + 1], wdp[4]); ffma2(acc, pB[j + 2], wdp[5]);
                ffma2(acc, pC[j], wdp[6]); ffma2(acc, pC[j + 1], wdp[7]); ffma2(acc, pC[j + 2], wdp[8]);
                o2[j] = acc;
                ffma2(ssp, acc, acc);
            }
            float2 sp = ull2f2(ssp);
            float ss = sp.x + sp.y;
            ss += __shfl_xor_sync(0xffffffffu, ss, 4);
            ss += __shfl_xor_sync(0xffffffffu, ss, 2);
            ss += __shfl_xor_sync(0xffffffffu, ss, 1);
            __syncwarp();
            // pair-permuted store: (o0,o4,o1,o5 | o2,o6,o3,o7) = o2[0],o2[1] | o2[2],o2[3]
            float2 f0 = ull2f2(o2[0]), f1 = ull2f2(o2[1]);
            float2 f2_ = ull2f2(o2[2]), f3 = ull2f2(o2[3]);
            float4* w4p = (float4*)(rr + row * 8);
            w4p[0] = make_float4(__uint_as_float(f2tf32(f0.x)), __uint_as_float(f2tf32(f0.y)),
                                 __uint_as_float(f2tf32(f1.x)), __uint_as_float(f2tf32(f1.y)));
            w4p[1] = make_float4(__uint_as_float(f2tf32(f2_.x)), __uint_as_float(f2tf32(f2_.y)),
                                 __uint_as_float(f2tf32(f3.x)), __uint_as_float(f2tf32(f3.y)));
            if ((lane & 7) == 0)
                Ns[ch_] = 1.f / fmaxf(sqrtf(ss), 1e-12f);
            __syncwarp();
        }
        // V -> transposed Vt in Ra (tf32)
#pragma unroll
        for (int it = 0; it < 3; it++) {
            int task = it * NTHR + tid;
            int ch = task % DIM;
            int row = task / DIM;
            const float* rr = Rd + ch * STRC;
            const float* wd = dw_w + (size_t)(2 * DIM + ch) * 9;
            ull wdp[9];
#pragma unroll
            for (int u = 0; u < 9; u++) wdp[u] = dup2(__ldg(wd + u));
            float A[8], B[8], C[8];
            ldrow(rr + row * 8, 1, B);
            ldrow(rr + (row - 1) * 8, row > 0, A);
            ldrow(rr + (row + 1) * 8, row < 7, C);
            ull pA[6], pB[6], pC[6];
            mkpairs(A, pA); mkpairs(B, pB); mkpairs(C, pC);
#pragma unroll
            for (int j = 0; j < 4; j++) {
                ull acc = 0ull;
                ffma2(acc, pA[j], wdp[0]); ffma2(acc, pA[j + 1], wdp[1]); ffma2(acc, pA[j + 2], wdp[2]);
                ffma2(acc, pB[j], wdp[3]); ffma2(acc, pB[j + 1], wdp[4]); ffma2(acc, pB[j + 2], wdp[5]);
                ffma2(acc, pC[j], wdp[6]); ffma2(acc, pC[j + 1], wdp[7]); ffma2(acc, pC[j + 2], wdp[8]);
                float2 f = ull2f2(acc);
                Ra[(row * 8 + j) * STRK + ch]     = __uint_as_float(f2tf32(f.x));
                Ra[(row * 8 + j + 4) * STRK + ch] = __uint_as_float(f2tf32(f.y));
            }
        }
    }
    __syncthreads();

    // ---- scores via mma.sync (pair lds64 fragments): S -> As (Rd) ----
    {
        float* As = Rd;
        const int gid = lane >> 2, tig = lane & 3;
#pragma unroll
        for (int i = 0; i < 3; i++) {
            int t = wid + 16 * i;
            int head = t >> 3, mt = (t >> 2) & 1, nt = t & 3;
            int bm = head * 32 + mt * 16, bn = head * 32 + nt * 8;
            float dacc[4] = {0.f, 0.f, 0.f, 0.f};
#pragma unroll
            for (int kc = 0; kc < 8; kc++) {
                uint32_t p0[2], p1[2], pb[2];
                uint32_t cofs = (kc * 8 + tig * 2) * 4;
                lds64(p0, sRb + ((bm + gid) * STRC) * 4 + cofs);
                lds64(p1, sRb + ((bm + gid + 8) * STRC) * 4 + cofs);
                lds64(pb, sRc + ((bn + gid) * STRC) * 4 + cofs);
                uint32_t areg[4] = {p0[0], p1[0], p0[1], p1[1]};
                mma16n8k8(dacc, areg, pb);
            }
            float tmp = __ldg(temperature + head);
            float iq0 = Ns[bm + gid] * tmp, iq8 = Ns[bm + gid + 8] * tmp;
            float ik0 = Ns[DIM + bn + 2 * tig], ik1 = Ns[DIM + bn + 2 * tig + 1];
            int d0 = 2 * tig, d1 = 2 * tig + 1;
            int p0o = nt * 8 + (d0 & 3) * 2 + ((d0 >> 2) & 1);
            int p1o = nt * 8 + (d1 & 3) * 2 + ((d1 >> 2) & 1);
            As[(bm + gid) * STRA + p0o]     = dacc[0] * iq0 * ik0;
            As[(bm + gid) * STRA + p1o]     = dacc[1] * iq0 * ik1;
            As[(bm + gid + 8) * STRA + p0o] = dacc[2] * iq8 * ik0;
            As[(bm + gid + 8) * STRA + p1o] = dacc[3] * iq8 * ik1;
        }
    }
    __syncthreads();

    // ---- softmax over row (order-invariant) ----
    if (tid < DIM) {
        float* arow = Rd + tid * STRA;
        float m = arow[0];
#pragma unroll
        for (int d = 1; d < 32; d++) m = fmaxf(m, arow[d]);
        float s = 0.f;
        float ev[32];
#pragma unroll
        for (int d = 0; d < 32; d++) { ev[d] = expf(arow[d] - m); s += ev[d]; }
        float inv = 1.f / s;
#pragma unroll
        for (int d = 0; d < 32; d++) arow[d] = __uint_as_float(f2tf32(ev[d] * inv));
    }
    __syncthreads();

    // ---- attn@v via mma.sync: O -> Rb B-swizzled tf32 ----
    {
        const uint32_t* Vu = (const uint32_t*)Ra;
        uint32_t* Ou = (uint32_t*)Rb;
        const int gid = lane >> 2, tig = lane & 3;
#pragma unroll
        for (int i = 0; i < 6; i++) {
            int t = wid + 16 * i;
            int head = t >> 4, mt = (t >> 3) & 1, nt = t & 7;
            int bm = head * 32 + mt * 16, bn = nt * 8;
            float dacc[4] = {0.f, 0.f, 0.f, 0.f};
#pragma unroll
            for (int kc = 0; kc < 4; kc++) {
                int kk = kc * 8;
                uint32_t p0[2], p1[2], breg[2];
                uint32_t cofs = (kk + tig * 2) * 4;
                lds64(p0, sRd + ((bm + gid) * STRA) * 4 + cofs);
                lds64(p1, sRd + ((bm + gid + 8) * STRA) * 4 + cofs);
                breg[0] = Vu[(bn + gid) * STRK + head * 32 + kk + tig];
                breg[1] = Vu[(bn + gid) * STRK + head * 32 + kk + tig + 4];
                uint32_t areg[4] = {p0[0], p1[0], p0[1], p1[1]};
                mma16n8k8(dacc, areg, breg);
            }
            int px = bn + 2 * tig;
            Ou[bswz_idx(bm + gid, px)]         = f2tf32(dacc[0]);
            Ou[bswz_idx(bm + gid, px + 1)]     = f2tf32(dacc[1]);
            Ou[bswz_idx(bm + gid + 8, px)]     = f2tf32(dacc[2]);
            Ou[bswz_idx(bm + gid + 8, px + 1)] = f2tf32(dacc[3]);
        }
    }
    __syncthreads();

    // ---- proj GEMM via mma.sync tf32, triple-buffered staging in Ra ----
    {
        const int gid = lane >> 2, tig = lane & 3;
        const int mgr = wid >> 2, ngr = wid & 3;
        const uint32_t bufs[3] = {sRa, sRa + PRJ_CHUNK * 4, sRa + 2 * PRJ_CHUNK * 4};
        float dacc[3][2][4];
#pragma unroll
        for (int mt = 0; mt < 3; mt++)
#pragma unroll
            for (int nt = 0; nt < 2; nt++)
#pragma unroll
                for (int q = 0; q < 4; q++) dacc[mt][nt][q] = 0.f;

        for (int e = tid; e < PRJ_CHUNK / 4; e += NTHR)
            cp16(bufs[0] + e * 16, g_projK + e * 4);
        cp_commit();
        for (int e = tid; e < PRJ_CHUNK / 4; e += NTHR)
            cp16(bufs[1] + e * 16, g_projK + PRJ_CHUNK + e * 4);
        cp_commit();

        for (int kc = 0; kc < 12; kc++) {
            if (kc < 11) cp_wait<1>(); else cp_wait<0>();
            __syncthreads();
            if (kc + 2 < 12) {
                uint32_t sN = bufs[(kc + 2) % 3];
                const uint32_t* src = g_projK + (kc + 2) * PRJ_CHUNK;
                for (int e = tid; e < PRJ_CHUNK / 4; e += NTHR)
                    cp16(sN + e * 16, src + e * 4);
                cp_commit();
            }
            const uint32_t sW = bufs[kc % 3];
#pragma unroll
            for (int ks = 0; ks < 2; ks++) {
                uint32_t bbase = sRb + (((kc * 2 + ks) * 4 + tig) * BSW) * 4;
                uint32_t breg[2][2];
#pragma unroll
                for (int nt = 0; nt < 2; nt++) {
                    int col = ngr * 16 + nt * 8 + gid;
                    lds64(breg[nt], bbase + col * 8);
                }
#pragma unroll
                for (int mt = 0; mt < 3; mt++) {
                    uint32_t areg[4];
                    lds128(areg, sW + (ks * 1536 + (mgr * 3 + mt) * 128 + lane * 4) * 4);
#pragma unroll
                    for (int nt = 0; nt < 2; nt++)
                        mma16n8k8(dacc[mt][nt], areg, breg[nt]);
                }
            }
        }

        // epilogue: fragments -> gmem with roll(+4,+4)
#pragma unroll
        for (int mt = 0; mt < 3; mt++) {
#pragma unroll
            for (int half = 0; half < 2; half++) {
                int o = mgr * 48 + mt * 16 + gid + half * 8;
                float* obase = out + ((size_t)(bi * DIM + o) * IMG) * IMG;
#pragma unroll
                for (int nt = 0; nt < 2; nt++) {
                    int p = ngr * 16 + nt * 8 + 2 * tig;
                    int i = p >> 3, j = p & 7;
                    int gh = (wh * WSZ + i + SHIFTV) & 255;
                    int gw0 = (ww * WSZ + j + SHIFTV) & 255;
                    int gw1 = (ww * WSZ + j + 1 + SHIFTV) & 255;
                    obase[gh * IMG + gw0] = dacc[mt][nt][half * 2];
                    obase[gh * IMG + gw1] = dacc[mt][nt][half * 2 + 1];
                }
            }
        }
    }
}

extern "C" void kernel_launch(void* const* d_in, const int* in_sizes, int n_in,
                              void* d_out, int out_size) {
    const float* x           = (const float*)d_in[0];
    const float* qkv_w       = (const float*)d_in[1];
    const float* dw_w        = (const float*)d_in[2];
    const float* proj_w      = (const float*)d_in[3];
    const float* temperature = (const float*)d_in[4];
    float* out = (float*)d_out;

    cudaFuncSetAttribute(attn_kernel, cudaFuncAttributeMaxDynamicSharedMemorySize,
                         SMEM_FLOATS * 4);
    wtrans_kernel<<<(640 * DIM + 255) / 256, 256>>>(qkv_w, proj_w);
    attn_kernel<<<4096, NTHR, SMEM_FLOATS * 4>>>(x, dw_w, temperature, out);
}